// round 10
// baseline (speedup 1.0000x reference)
#include <cuda_runtime.h>
#include <math.h>

#define BATCH 256

// ------------------- scratch (alloc-free rule: device globals) -------------------
__device__ float2 g_p1[BATCH * 32 * 4096];  // conv1 out, parity-split, {hi,lo}
__device__ float2 g_p2[BATCH * 64 * 1024];  // conv2 out {hi,lo}
__device__ float2 g_p3[BATCH * 64 * 1024];  // conv3 out {hi,lo}
__device__ float2 g_z2[BATCH * 32 * 1024];  // z {hi,lo}
__device__ float  g_q  [BATCH * 32 * 1024]; // quantized latent (tf32-rounded)
__device__ float  g_dc1[BATCH * 64 * 1024]; // dec1 out (tf32-rounded)
__device__ float  g_dd1[BATCH * 32 * 4096]; // deconv1 out (fp32)
__device__ float  g_lpart[2048];
__device__ float  g_wb [131072];            // prepped weights hi (co' order)
__device__ float  g_wbl[131072];            // weights lo
__device__ float  g_cbh[16384];             // codebook hi
__device__ float  g_cbl[16384];             // codebook lo
__device__ float  g_cn[512];                // codebook norms

#define OFF_C2  0
#define OFF_C3  32768
#define OFF_C4  69632
#define OFF_D1  71680
#define OFF_T1  90112

// ------------------- tf32 helpers -------------------
__device__ __forceinline__ unsigned f2tf32(float x) {
    unsigned r;
    asm("cvt.rna.tf32.f32 %0, %1;" : "=r"(r) : "f"(x));
    return r;
}

__device__ __forceinline__ void mma_tf32(float& c0, float& c1, float& c2, float& c3,
                                         unsigned a0, unsigned a1, unsigned a2, unsigned a3,
                                         unsigned b0, unsigned b1) {
    asm volatile("mma.sync.aligned.m16n8k8.row.col.f32.tf32.tf32.f32 "
                 "{%0,%1,%2,%3}, {%4,%5,%6,%7}, {%8,%9}, {%0,%1,%2,%3};"
                 : "+f"(c0), "+f"(c1), "+f"(c2), "+f"(c3)
                 : "r"(a0), "r"(a1), "r"(a2), "r"(a3), "r"(b0), "r"(b1));
}

__host__ __device__ constexpr int pick_pw(int hh, int w, int m, int a, int b) {
    int p = w;
    while (((hh * p) % m) != a && ((hh * p) % m) != b) p++;
    return p;
}

// ------------------- fused prep: weights hi/lo (co'-order), codebook, norms -------------------
__global__ void k_prep_all(const float* __restrict__ ew2, const float* __restrict__ ew3,
                           const float* __restrict__ ew4, const float* __restrict__ dw1,
                           const float* __restrict__ tw1, const float* __restrict__ cb,
                           float* __restrict__ wbh, float* __restrict__ wbl,
                           float* __restrict__ cbh, float* __restrict__ cbl,
                           float* __restrict__ cn) {
    const int b = blockIdx.x, t = threadIdx.x;
    float v; int oidx;
    if (b < 128) {                       // conv2 parity-split: [grp4][plane4][tap4][cig8][co'64]
        int i = b * 256 + t;
        int co = i & 63, r = i >> 6, cig = r & 7, r2 = r >> 3;
        int tap = r2 & 3, r3 = r2 >> 2, plane = r3 & 3, grp = r3 >> 2;
        int py = plane >> 1, px = plane & 1;
        int ty = tap >> 1, tx = tap & 1;
        int ky = (py == 0) ? (ty ? 3 : 1) : (ty ? 2 : 0);
        int kx = (px == 0) ? (tx ? 3 : 1) : (tx ? 2 : 0);
        int ci = grp * 8 + cig;
        int cop = ((co & 7) << 3) | (co >> 3);
        v = ew2[(co * 32 + ci) * 16 + ky * 4 + kx]; oidx = OFF_C2 + (i & ~63) + cop;
    } else if (b < 272) {                // conv3: [grp8][tap9][cig8][co'64]
        int i = (b - 128) * 256 + t;
        int co = i & 63, r = i >> 6, cig = r & 7, r2 = r >> 3, tap = r2 % 9, grp = r2 / 9;
        int ci = grp * 8 + cig;
        int cop = ((co & 7) << 3) | (co >> 3);
        v = ew3[(co * 64 + ci) * 9 + tap]; oidx = OFF_C3 + (i & ~63) + cop;
    } else if (b < 280) {                // conv4: [grp8][cig8][co'32]
        int i = (b - 272) * 256 + t;
        int co = i & 31, r = i >> 5, cig = r & 7, grp = r >> 3;
        int ci = grp * 8 + cig;
        int cop = ((co & 7) << 2) | (co >> 3);
        v = ew4[co * 64 + ci]; oidx = OFF_C4 + (i & ~31) + cop;
    } else if (b < 352) {                // dec1: [grp4][tap9][cig8][co'64]
        int i = (b - 280) * 256 + t;
        int co = i & 63, r = i >> 6, cig = r & 7, r2 = r >> 3, tap = r2 % 9, grp = r2 / 9;
        int ci = grp * 8 + cig;
        int cop = ((co & 7) << 3) | (co >> 3);
        v = dw1[(co * 32 + ci) * 9 + tap]; oidx = OFF_D1 + (i & ~63) + cop;
    } else if (b < 480) {                // deconv1: [cls4][grp8][tap4][cig8][co'32]
        int i = (b - 352) * 256 + t;
        int co = i & 31, r = i >> 5, cig = r & 7, r2 = r >> 3, tap = r2 & 3, r3 = r2 >> 2;
        int grp = r3 & 7, cls = r3 >> 3;
        int py = cls >> 1, px = cls & 1;
        int ty = tap >> 1, tx = tap & 1;
        int ky = ty ? 3 - py : 1 - py;
        int kx = tx ? 3 - px : 1 - px;
        int ci = grp * 8 + cig;
        int cop = ((co & 7) << 2) | (co >> 3);
        v = tw1[(ci * 32 + co) * 16 + ky * 4 + kx]; oidx = OFF_T1 + (i & ~31) + cop;
    } else if (b < 544) {                // codebook hi/lo (natural order)
        int i = (b - 480) * 256 + t;
        float cv = cb[i];
        unsigned hi = f2tf32(cv);
        cbh[i] = __uint_as_float(hi);
        cbl[i] = __uint_as_float(f2tf32(cv - __uint_as_float(hi)));
        return;
    } else {                             // norms
        int k = (b - 544) * 256 + t;
        if (k < 512) {
            float s = 0.f;
            const float* c = cb + k * 32;
            #pragma unroll
            for (int d = 0; d < 32; d++) s = fmaf(c[d], c[d], s);
            cn[k] = s;
        }
        return;
    }
    unsigned hi = f2tf32(v);
    wbh[oidx] = __uint_as_float(hi);
    wbl[oidx] = __uint_as_float(f2tf32(v - __uint_as_float(hi)));
}

// ------------------- tf32 implicit-GEMM, halo-tile staging, vectorized fragments -------------------
// X3: input is interleaved float2 {hi,lo}; A fragments via LDS.64; B via LDS.128 (co' order).
// OUTM: 0 fp32, 1 tf32-rounded, 2 float2 {hi,lo}.
template<int CIN, int HIN, int COUT, int S, int K, int P, int NTAPS,
         bool DECONV, bool PSPLIT, int OS, int W, bool X3, bool RELU, int OUTM>
__global__ void __launch_bounds__(256, 2)
k_igemm(const void* __restrict__ inv, const float* __restrict__ wbh,
        const float* __restrict__ wbl, const float* __restrict__ bias,
        void* __restrict__ outv) {
    constexpr int G8 = CIN / 8;
    constexpr int NG = PSPLIT ? G8 * 4 : G8;
    constexpr int NT = COUT / 8;
    constexpr int HH0 = PSPLIT ? 9 : 7 * S + (DECONV ? 2 : K);
    constexpr int HW  = PSPLIT ? 33 : 31 * S + (DECONV ? 2 : K);
    constexpr int HH  = (X3 && (HH0 % 2 == 0)) ? HH0 + 1 : HH0;
    constexpr int PW  = X3 ? pick_pw(HH, HW, 16, 4, 12) : pick_pw(HH, HW, 32, 8, 24);
    constexpr int CHS = HH * PW;            // elements (float2 if X3 else float)
    constexpr int BP2 = NT * 8 + 4;
    constexpr int ASZ = 8 * CHS;
    constexpr int BSZ = NTAPS * 8 * BP2;
    constexpr int AS  = PSPLIT ? 1 : S;

    extern __shared__ float sm[];
    float2* A2 = (float2*)sm;
    float*  A1 = sm;
    float*  Bh = sm + (X3 ? 2 * ASZ : ASZ);
    float*  Bl = Bh + BSZ;                  // X3 only

    const int t = threadIdx.x, lane = t & 31, wrp = t >> 5;
    const int g = lane >> 2, tg = lane & 3;
    const int n = blockIdx.z;
    const int m0 = blockIdx.x * 256;
    const int r0 = blockIdx.x * 8;

    int cpy = 0, cpx = 0, cls = 0;
    if (DECONV) { cls = blockIdx.y; cpy = cls >> 1; cpx = cls & 1; }

    int aoff[4];
    #pragma unroll
    for (int q = 0; q < 4; q++) {
        int ml = wrp * 32 + (q >> 1) * 16 + g + (q & 1) * 8;
        int oyl = ml >> 5, ox = ml & 31;
        aoff[q] = tg * CHS + (oyl * AS) * PW + ox * AS;
    }

    float acc[NT][2][4];
    #pragma unroll
    for (int i = 0; i < NT; i++)
        #pragma unroll
        for (int mt = 0; mt < 2; mt++)
            #pragma unroll
            for (int j = 0; j < 4; j++) acc[i][mt][j] = 0.f;

    for (int sg = 0; sg < NG; sg++) {
        const int grp   = PSPLIT ? (sg >> 2) : sg;
        const int plane = PSPLIT ? (sg & 3) : 0;
        const int DYMIN = PSPLIT ? -(plane >> 1) : (DECONV ? cpy - 1 : -P);
        const int DXMIN = PSPLIT ? -(plane & 1)  : (DECONV ? cpx - 1 : -P);
        const int ci0 = grp * 8;
        __syncthreads();
        // ---- stage A halo ----
        for (int i = t; i < 8 * HH * HW; i += 256) {
            int ch = i / (HH * HW), rem = i % (HH * HW);
            int rr = rem / HW, cc = rem % HW;
            int iy = (PSPLIT ? r0 : r0 * S) + DYMIN + rr;
            int ix = DXMIN + cc;
            bool ok = (unsigned)iy < (unsigned)HIN && (unsigned)ix < (unsigned)HIN;
            long gi;
            if (PSPLIT)
                gi = (((long)n * CIN + ci0 + ch) * 4 + plane) * (HIN * HIN)
                   + (long)iy * HIN + ix;
            else
                gi = ((long)n * CIN + ci0 + ch) * (HIN * HIN) + (long)iy * HIN + ix;
            int si = ch * CHS + rr * PW + cc;
            if (X3) A2[si] = ok ? __ldg((const float2*)inv + gi) : make_float2(0.f, 0.f);
            else    A1[si] = ok ? __ldg((const float*)inv + gi) : 0.f;
        }
        // ---- stage B ----
        {
            const long wo = (DECONV ? (long)cls * NG * NTAPS * 8 * COUT : 0)
                          + (long)sg * NTAPS * 8 * COUT;
            for (int i = t; i < NTAPS * 8 * COUT; i += 256) {
                int tap = i / (8 * COUT), rem = i % (8 * COUT);
                int k = rem / COUT, c = rem % COUT;
                int si = tap * 8 * BP2 + k * BP2 + c;
                Bh[si] = wbh[wo + i];
                if (X3) Bl[si] = wbl[wo + i];
            }
        }
        __syncthreads();

        // ---- barrier-free tap loop ----
        for (int tap = 0; tap < NTAPS; tap++) {
            int ty, tx;
            if (PSPLIT)      { ty = tap >> 1;                   tx = tap & 1; }
            else if (DECONV) { ty = (cpy - (tap >> 1)) - DYMIN; tx = (cpx - (tap & 1)) - DXMIN; }
            else             { ty = tap / K;                    tx = tap % K; }
            const int toff = ty * PW + tx;

            unsigned ah[2][4], al[2][4];
            #pragma unroll
            for (int q = 0; q < 4; q++) {
                int si = aoff[q] + toff;
                int mt = q >> 1, h = q & 1;
                if (X3) {
                    float2 v0 = A2[si];
                    float2 v1 = A2[si + 4 * CHS];
                    ah[mt][h]     = __float_as_uint(v0.x); al[mt][h]     = __float_as_uint(v0.y);
                    ah[mt][2 + h] = __float_as_uint(v1.x); al[mt][2 + h] = __float_as_uint(v1.y);
                } else {
                    ah[mt][h]     = __float_as_uint(A1[si]);
                    ah[mt][2 + h] = __float_as_uint(A1[si + 4 * CHS]);
                }
            }

            const float* Bt  = Bh + tap * 8 * BP2;
            const float* Btl = Bl + tap * 8 * BP2;
            #pragma unroll
            for (int nh = 0; nh < NT / 4; nh++) {
                float4 h0 = *(const float4*)(Bt + tg * BP2 + g * NT + nh * 4);
                float4 h1 = *(const float4*)(Bt + (tg + 4) * BP2 + g * NT + nh * 4);
                float h0a[4] = {h0.x, h0.y, h0.z, h0.w};
                float h1a[4] = {h1.x, h1.y, h1.z, h1.w};
                float l0a[4], l1a[4];
                if (X3) {
                    float4 l0 = *(const float4*)(Btl + tg * BP2 + g * NT + nh * 4);
                    float4 l1 = *(const float4*)(Btl + (tg + 4) * BP2 + g * NT + nh * 4);
                    l0a[0]=l0.x; l0a[1]=l0.y; l0a[2]=l0.z; l0a[3]=l0.w;
                    l1a[0]=l1.x; l1a[1]=l1.y; l1a[2]=l1.z; l1a[3]=l1.w;
                }
                #pragma unroll
                for (int ntl = 0; ntl < 4; ntl++) {
                    const int nt = nh * 4 + ntl;
                    unsigned bh0 = __float_as_uint(h0a[ntl]);
                    unsigned bh1 = __float_as_uint(h1a[ntl]);
                    #pragma unroll
                    for (int mt = 0; mt < 2; mt++) {
                        if (X3) {
                            unsigned bl0 = __float_as_uint(l0a[ntl]);
                            unsigned bl1 = __float_as_uint(l1a[ntl]);
                            mma_tf32(acc[nt][mt][0], acc[nt][mt][1], acc[nt][mt][2], acc[nt][mt][3],
                                     al[mt][0], al[mt][1], al[mt][2], al[mt][3], bh0, bh1);
                            mma_tf32(acc[nt][mt][0], acc[nt][mt][1], acc[nt][mt][2], acc[nt][mt][3],
                                     ah[mt][0], ah[mt][1], ah[mt][2], ah[mt][3], bl0, bl1);
                        }
                        mma_tf32(acc[nt][mt][0], acc[nt][mt][1], acc[nt][mt][2], acc[nt][mt][3],
                                 ah[mt][0], ah[mt][1], ah[mt][2], ah[mt][3], bh0, bh1);
                    }
                }
            }
        }
    }

    // ---- epilogue ----
    int eoy[4], eox[4];
    #pragma unroll
    for (int q = 0; q < 4; q++) {
        int m = m0 + wrp * 32 + (q >> 1) * 16 + ((q & 1) ? g + 8 : g);
        eoy[q] = (m >> 5) * OS + cpy;
        eox[q] = (m & 31) * OS + cpx;
    }
    #pragma unroll
    for (int nt = 0; nt < NT; nt++) {
        int co = nt * 8 + 2 * tg;
        float b0 = __ldg(bias + co), b1 = __ldg(bias + co + 1);
        #pragma unroll
        for (int mt = 0; mt < 2; mt++) {
            #pragma unroll
            for (int hh = 0; hh < 2; hh++) {
                int qd = mt * 2 + hh;
                float v0 = acc[nt][mt][hh * 2 + 0] + b0;
                float v1 = acc[nt][mt][hh * 2 + 1] + b1;
                if (RELU) { v0 = fmaxf(v0, 0.f); v1 = fmaxf(v1, 0.f); }
                long ob = (((long)n * COUT + co) * W + eoy[qd]) * W + eox[qd];
                long ob1 = ob + (long)W * W;
                if (OUTM == 0) {
                    ((float*)outv)[ob] = v0; ((float*)outv)[ob1] = v1;
                } else if (OUTM == 1) {
                    ((float*)outv)[ob]  = __uint_as_float(f2tf32(v0));
                    ((float*)outv)[ob1] = __uint_as_float(f2tf32(v1));
                } else {
                    unsigned h0 = f2tf32(v0), h1 = f2tf32(v1);
                    float l0 = __uint_as_float(f2tf32(v0 - __uint_as_float(h0)));
                    float l1 = __uint_as_float(f2tf32(v1 - __uint_as_float(h1)));
                    ((float2*)outv)[ob]  = make_float2(__uint_as_float(h0), l0);
                    ((float2*)outv)[ob1] = make_float2(__uint_as_float(h1), l1);
                }
            }
        }
    }
}

// ------------------- conv1 (scalar, CIN=1), parity-split float2 {hi,lo} output -------------------
template<int CIN, int HIN, int K, int S, int P, int COUT, int CT, int ST>
__global__ void k_conv1(const float* __restrict__ in, const float* __restrict__ w,
                        const float* __restrict__ bias, float2* __restrict__ out) {
    constexpr int HOUT = (HIN + 2 * P - K) / S + 1;
    constexpr int KK = K * K;
    __shared__ float sw[CT * CIN * KK];
    const int co0 = blockIdx.y * CT;
    const int n   = blockIdx.z;
    const int t   = threadIdx.x;
    for (int i = t; i < CT * CIN * KK; i += 256) {
        int c = i / (CIN * KK), rest = i % (CIN * KK);
        sw[i] = w[(co0 + c) * CIN * KK + rest];
    }
    __syncthreads();

    const int p0  = (blockIdx.x * 256 + t) * ST;
    const int oy  = p0 / HOUT;
    const int ox0 = p0 % HOUT;

    float acc[CT][ST];
    #pragma unroll
    for (int c = 0; c < CT; c++) {
        float bv = bias[co0 + c];
        #pragma unroll
        for (int s = 0; s < ST; s++) acc[c][s] = bv;
    }

    const float* ib = in + (long)n * CIN * HIN * HIN;
    for (int ci = 0; ci < CIN; ci++) {
        const float* ic = ib + ci * HIN * HIN;
        #pragma unroll
        for (int ky = 0; ky < K; ky++) {
            int iy = oy * S - P + ky;
            if ((unsigned)iy < (unsigned)HIN) {
                const float* row = ic + iy * HIN;
                #pragma unroll
                for (int kx = 0; kx < K; kx++) {
                    float xv[ST];
                    #pragma unroll
                    for (int s = 0; s < ST; s++) {
                        int ix = (ox0 + s) * S - P + kx;
                        xv[s] = ((unsigned)ix < (unsigned)HIN) ? row[ix] : 0.f;
                    }
                    #pragma unroll
                    for (int c = 0; c < CT; c++) {
                        float wv = sw[(c * CIN + ci) * KK + ky * K + kx];
                        #pragma unroll
                        for (int s = 0; s < ST; s++)
                            acc[c][s] = fmaf(xv[s], wv, acc[c][s]);
                    }
                }
            }
        }
    }

    const int py = oy & 1, u = oy >> 1;
    #pragma unroll
    for (int c = 0; c < CT; c++) {
        #pragma unroll
        for (int s = 0; s < ST; s++) {
            int ox = ox0 + s;
            int plane = py * 2 + (ox & 1);
            long ob = ((((long)n * COUT + co0 + c) * 4 + plane) * 32 + u) * 32 + (ox >> 1);
            float v = fmaxf(acc[c][s], 0.f);
            unsigned hi = f2tf32(v);
            out[ob] = make_float2(__uint_as_float(hi),
                                  __uint_as_float(f2tf32(v - __uint_as_float(hi))));
        }
    }
}

// ------------------- deconv2: [256,32,64,64] -> [256,1,128,128], sigmoid -------------------
__global__ void k_deconv2(const float* __restrict__ in, const float* __restrict__ w,
                          const float* __restrict__ bias, float* __restrict__ out) {
    __shared__ float sw[512];
    const int t = threadIdx.x;
    const int n = blockIdx.z;
    for (int i = t; i < 512; i += 256) sw[i] = w[i];
    __syncthreads();

    const int ti = blockIdx.x * 256 + t;
    const int ty = ti >> 4, tx = ti & 15;
    const float bv = __ldg(bias);

    float acc[4][8];
    #pragma unroll
    for (int r = 0; r < 4; r++)
        #pragma unroll
        for (int c = 0; c < 8; c++) acc[r][c] = 0.f;

    const float* ib = in + (long)n * 32 * 4096;
    for (int ci = 0; ci < 32; ci++) {
        const float* ic = ib + ci * 4096;
        float xv[4][6];
        #pragma unroll
        for (int rr = 0; rr < 4; rr++) {
            int iy = 2 * ty - 1 + rr;
            bool vy = (unsigned)iy < 64u;
            const float* row = ic + iy * 64;
            int c0 = 4 * tx - 1;
            xv[rr][0] = (vy && c0 >= 0) ? row[c0] : 0.f;
            if (vy) {
                float4 m4 = *(const float4*)(row + 4 * tx);
                xv[rr][1] = m4.x; xv[rr][2] = m4.y; xv[rr][3] = m4.z; xv[rr][4] = m4.w;
            } else {
                xv[rr][1] = xv[rr][2] = xv[rr][3] = xv[rr][4] = 0.f;
            }
            int c5 = 4 * tx + 4;
            xv[rr][5] = (vy && c5 < 64) ? row[c5] : 0.f;
        }
        float wr[16];
        #pragma unroll
        for (int k = 0; k < 16; k++) wr[k] = sw[ci * 16 + k];
        #pragma unroll
        for (int r = 0; r < 4; r++) {
            const int pyy = r & 1;
            const int rowA = (r >> 1) + pyy + 1, rowB = rowA - 1;
            #pragma unroll
            for (int c = 0; c < 8; c++) {
                const int pxx = c & 1;
                const int colA = (c >> 1) + pxx + 1, colB = colA - 1;
                float a = acc[r][c];
                a = fmaf(xv[rowA][colA], wr[(1 - pyy) * 4 + (1 - pxx)], a);
                a = fmaf(xv[rowA][colB], wr[(1 - pyy) * 4 + (3 - pxx)], a);
                a = fmaf(xv[rowB][colA], wr[(3 - pyy) * 4 + (1 - pxx)], a);
                a = fmaf(xv[rowB][colB], wr[(3 - pyy) * 4 + (3 - pxx)], a);
                acc[r][c] = a;
            }
        }
    }

    float* ob = out + (long)n * 16384;
    #pragma unroll
    for (int r = 0; r < 4; r++) {
        int oy = 4 * ty + r;
        float v[8];
        #pragma unroll
        for (int c = 0; c < 8; c++)
            v[c] = 1.f / (1.f + expf(-(acc[r][c] + bv)));
        *(float4*)(ob + oy * 128 + 8 * tx)     = make_float4(v[0], v[1], v[2], v[3]);
        *(float4*)(ob + oy * 128 + 8 * tx + 4) = make_float4(v[4], v[5], v[6], v[7]);
    }
}

// ------------------- VQ on tensor cores (3xTF32, float2 z, vectorized codebook frags) -------------------
__global__ void k_vq_tc(const float2* __restrict__ z2, const float* __restrict__ cb,
                        const float* __restrict__ cbh, const float* __restrict__ cbl,
                        const float* __restrict__ cn,
                        float* __restrict__ q, float* __restrict__ lpart) {
    __shared__ unsigned As[2][32][136];
    __shared__ unsigned Bs[2][32][40];   // [hi/lo][d][kk'] kk' = (kk&7)*4 + (kk>>3)
    __shared__ float scn[32];
    __shared__ int sidx[128];
    __shared__ float red[256];
    const int t = threadIdx.x, lane = t & 31, wrp = t >> 5;
    const int g = lane >> 2, tg = lane & 3;
    const int n  = blockIdx.x >> 3;
    const int p0 = (blockIdx.x & 7) * 128;
    const int mw = wrp * 16;

    for (int i = t; i < 4096; i += 256) {
        int d = i >> 7, m = i & 127;
        long zi = ((long)n * 32 + d) * 1024 + p0 + m;
        float2 v = z2[zi];
        As[0][d][m] = __float_as_uint(v.x);
        As[1][d][m] = __float_as_uint(v.y);
    }
    __syncthreads();

    unsigned ah[4][4], al[4][4];
    #pragma unroll
    for (int s = 0; s < 4; s++) {
        ah[s][0] = As[0][s * 8 + tg][mw + g];     ah[s][1] = As[0][s * 8 + tg][mw + g + 8];
        ah[s][2] = As[0][s * 8 + tg + 4][mw + g]; ah[s][3] = As[0][s * 8 + tg + 4][mw + g + 8];
        al[s][0] = As[1][s * 8 + tg][mw + g];     al[s][1] = As[1][s * 8 + tg][mw + g + 8];
        al[s][2] = As[1][s * 8 + tg + 4][mw + g]; al[s][3] = As[1][s * 8 + tg + 4][mw + g + 8];
    }

    float best0 = 3.4e38f, best1 = 3.4e38f;
    int bidx0 = 0, bidx1 = 0;

    for (int ch = 0; ch < 16; ch++) {
        const int k0 = ch * 32;
        __syncthreads();
        for (int i = t; i < 1024; i += 256) {
            int d = i & 31, kk = i >> 5;
            int kkp = ((kk & 7) << 2) | (kk >> 3);
            Bs[0][d][kkp] = __float_as_uint(cbh[(k0 + kk) * 32 + d]);
            Bs[1][d][kkp] = __float_as_uint(cbl[(k0 + kk) * 32 + d]);
        }
        if (t < 32) scn[t] = cn[k0 + t];
        __syncthreads();

        float ac[4][4];
        #pragma unroll
        for (int nt = 0; nt < 4; nt++)
            #pragma unroll
            for (int j = 0; j < 4; j++) ac[nt][j] = 0.f;

        #pragma unroll
        for (int s = 0; s < 4; s++) {
            uint4 b0h = *(const uint4*)(&Bs[0][s * 8 + tg][g * 4]);
            uint4 b1h = *(const uint4*)(&Bs[0][s * 8 + tg + 4][g * 4]);
            uint4 b0l = *(const uint4*)(&Bs[1][s * 8 + tg][g * 4]);
            uint4 b1l = *(const uint4*)(&Bs[1][s * 8 + tg + 4][g * 4]);
            unsigned bh0[4] = {b0h.x, b0h.y, b0h.z, b0h.w};
            unsigned bh1[4] = {b1h.x, b1h.y, b1h.z, b1h.w};
            unsigned bl0[4] = {b0l.x, b0l.y, b0l.z, b0l.w};
            unsigned bl1[4] = {b1l.x, b1l.y, b1l.z, b1l.w};
            #pragma unroll
            for (int nt = 0; nt < 4; nt++) {
                mma_tf32(ac[nt][0], ac[nt][1], ac[nt][2], ac[nt][3],
                         al[s][0], al[s][1], al[s][2], al[s][3], bh0[nt], bh1[nt]);
                mma_tf32(ac[nt][0], ac[nt][1], ac[nt][2], ac[nt][3],
                         ah[s][0], ah[s][1], ah[s][2], ah[s][3], bl0[nt], bl1[nt]);
                mma_tf32(ac[nt][0], ac[nt][1], ac[nt][2], ac[nt][3],
                         ah[s][0], ah[s][1], ah[s][2], ah[s][3], bh0[nt], bh1[nt]);
            }
        }

        #pragma unroll
        for (int nt = 0; nt < 4; nt++) {
            int kc0 = k0 + nt * 8 + 2 * tg, kc1 = kc0 + 1;
            float c0 = scn[nt * 8 + 2 * tg], c1 = scn[nt * 8 + 2 * tg + 1];
            float d00 = fmaf(-2.f, ac[nt][0], c0), d01 = fmaf(-2.f, ac[nt][1], c1);
            float d10 = fmaf(-2.f, ac[nt][2], c0), d11 = fmaf(-2.f, ac[nt][3], c1);
            if (d00 < best0) { best0 = d00; bidx0 = kc0; }
            if (d01 < best0) { best0 = d01; bidx0 = kc1; }
            if (d10 < best1) { best1 = d10; bidx1 = kc0; }
            if (d11 < best1) { best1 = d11; bidx1 = kc1; }
        }
    }

    #pragma unroll
    for (int off = 1; off < 4; off <<= 1) {
        float ob; int oi;
        ob = __shfl_down_sync(0xffffffffu, best0, off, 4);
        oi = __shfl_down_sync(0xffffffffu, bidx0, off, 4);
        if (ob < best0 || (ob == best0 && oi < bidx0)) { best0 = ob; bidx0 = oi; }
        ob = __shfl_down_sync(0xffffffffu, best1, off, 4);
        oi = __shfl_down_sync(0xffffffffu, bidx1, off, 4);
        if (ob < best1 || (ob == best1 && oi < bidx1)) { best1 = ob; bidx1 = oi; }
    }
    if (tg == 0) { sidx[mw + g] = bidx0; sidx[mw + g + 8] = bidx1; }
    __syncthreads();

    float lsum = 0.f;
    for (int i = t; i < 4096; i += 256) {
        int d = i >> 7, m = i & 127;
        long zi = ((long)n * 32 + d) * 1024 + p0 + m;
        float qv = __ldg(cb + sidx[m] * 32 + d);
        float2 zv2 = z2[zi];
        float zv = zv2.x + zv2.y;
        q[zi] = __uint_as_float(f2tf32(qv));
        float e = qv - zv;
        lsum = fmaf(e, e, lsum);
    }
    red[t] = lsum;
    __syncthreads();
    for (int s = 128; s > 0; s >>= 1) {
        if (t < s) red[t] += red[t + s];
        __syncthreads();
    }
    if (t == 0) lpart[blockIdx.x] = red[0];
}

// deterministic fixed-order final reduction: vq_loss = 1.26 * mean
__global__ void k_loss(const float* __restrict__ lpart, float* __restrict__ out,
                       int out_size) {
    __shared__ float red[256];
    const int t = threadIdx.x;
    float s = 0.f;
    #pragma unroll
    for (int j = 0; j < 8; j++) s += lpart[t + 256 * j];
    red[t] = s;
    __syncthreads();
    for (int st = 128; st > 0; st >>= 1) {
        if (t < st) red[t] += red[t + st];
        __syncthreads();
    }
    if (t == 0) out[out_size - 1] = 1.26f * red[0] / 8388608.0f;
}

// ------------------- launch -------------------
extern "C" void kernel_launch(void* const* d_in, const int* in_sizes, int n_in,
                              void* d_out, int out_size) {
    const float* x   = (const float*)d_in[0];
    const float* ew1 = (const float*)d_in[1];  const float* eb1 = (const float*)d_in[2];
    const float* ew2 = (const float*)d_in[3];  const float* eb2 = (const float*)d_in[4];
    const float* ew3 = (const float*)d_in[5];  const float* eb3 = (const float*)d_in[6];
    const float* ew4 = (const float*)d_in[7];  const float* eb4 = (const float*)d_in[8];
    const float* cb  = (const float*)d_in[9];
    const float* dw1 = (const float*)d_in[10]; const float* db1 = (const float*)d_in[11];
    const float* tw1 = (const float*)d_in[12]; const float* tb1 = (const float*)d_in[13];
    const float* tw2 = (const float*)d_in[14]; const float* tb2 = (const float*)d_in[15];
    float* out = (float*)d_out;

    float2 *pp1, *pp2, *pp3, *pz2;
    float *pq, *pdc1, *pdd1, *pl, *pwb, *pwbl, *pcbh, *pcbl, *pcn;
    cudaGetSymbolAddress((void**)&pp1, g_p1);
    cudaGetSymbolAddress((void**)&pp2, g_p2);
    cudaGetSymbolAddress((void**)&pp3, g_p3);
    cudaGetSymbolAddress((void**)&pz2, g_z2);
    cudaGetSymbolAddress((void**)&pq,  g_q);
    cudaGetSymbolAddress((void**)&pdc1, g_dc1);
    cudaGetSymbolAddress((void**)&pdd1, g_dd1);
    cudaGetSymbolAddress((void**)&pl,  g_lpart);
    cudaGetSymbolAddress((void**)&pwb, g_wb);  cudaGetSymbolAddress((void**)&pwbl, g_wbl);
    cudaGetSymbolAddress((void**)&pcbh, g_cbh); cudaGetSymbolAddress((void**)&pcbl, g_cbl);
    cudaGetSymbolAddress((void**)&pcn, g_cn);

    auto kc2 = k_igemm<32, 32, 64, 1, 2, 0, 4, false, true,  1, 32, true,  true,  2>;
    auto kc3 = k_igemm<64, 32, 64, 1, 3, 1, 9, false, false, 1, 32, true,  true,  2>;
    auto kc4 = k_igemm<64, 32, 32, 1, 1, 0, 1, false, false, 1, 32, true,  false, 2>;
    auto kd1 = k_igemm<32, 32, 64, 1, 3, 1, 9, false, false, 1, 32, false, true,  1>;
    auto kt1 = k_igemm<64, 32, 32, 1, 1, 0, 4, true,  false, 2, 64, false, true,  0>;
    const int SM_C2 = 38144, SM_C3 = 64512, SM_C4 = 23040, SM_D1 = 31104, SM_T1 = 16128;
    cudaFuncSetAttribute(kc2, cudaFuncAttributeMaxDynamicSharedMemorySize, SM_C2);
    cudaFuncSetAttribute(kc3, cudaFuncAttributeMaxDynamicSharedMemorySize, SM_C3);
    cudaFuncSetAttribute(kc4, cudaFuncAttributeMaxDynamicSharedMemorySize, SM_C4);
    cudaFuncSetAttribute(kd1, cudaFuncAttributeMaxDynamicSharedMemorySize, SM_D1);
    cudaFuncSetAttribute(kt1, cudaFuncAttributeMaxDynamicSharedMemorySize, SM_T1);

    k_prep_all<<<546, 256>>>(ew2, ew3, ew4, dw1, tw1, cb, pwb, pwbl, pcbh, pcbl, pcn);

    // Encoder (conv1 writes parity-split float2 planes)
    k_conv1<1, 128, 4, 2, 1, 32, 8, 4><<<dim3(4, 4, BATCH), 256>>>(x, ew1, eb1, pp1);
    kc2<<<dim3(4, 1, BATCH), 256, SM_C2>>>(pp1, pwb + OFF_C2, pwbl + OFF_C2, eb2, pp2);
    kc3<<<dim3(4, 1, BATCH), 256, SM_C3>>>(pp2, pwb + OFF_C3, pwbl + OFF_C3, eb3, pp3);
    kc4<<<dim3(4, 1, BATCH), 256, SM_C4>>>(pp3, pwb + OFF_C4, pwbl + OFF_C4, eb4, pz2);

    // VQ
    k_vq_tc<<<2048, 256>>>(pz2, cb, pcbh, pcbl, pcn, pq, pl);

    // Decoder
    kd1<<<dim3(4, 1, BATCH), 256, SM_D1>>>(pq, pwb + OFF_D1, pwbl + OFF_D1, db1, pdc1);
    kt1<<<dim3(4, 4, BATCH), 256, SM_T1>>>(pdc1, pwb + OFF_T1, pwbl + OFF_T1, tb1, pdd1);
    k_deconv2<<<dim3(2, 1, BATCH), 256>>>(pdd1, tw2, tb2, out);

    k_loss<<<1, 256>>>(pl, out, out_size);
}

// round 11
// speedup vs baseline: 1.0423x; 1.0423x over previous
#include <cuda_runtime.h>
#include <math.h>

#define BATCH 256

// ------------------- scratch (alloc-free rule: device globals) -------------------
__device__ float g_a [BATCH * 32 * 64 * 64];  // conv1 out hi (parity-split) / deconv1 out
__device__ float g_al[BATCH * 32 * 64 * 64];  // conv1 out lo (parity-split)
__device__ float g_b [BATCH * 64 * 32 * 32];  // conv2 out hi
__device__ float g_bl[BATCH * 64 * 32 * 32];  // conv2 out lo
__device__ float g_c [BATCH * 64 * 32 * 32];  // conv3 out hi / dec1 out (tf32)
__device__ float g_cl[BATCH * 64 * 32 * 32];  // conv3 out lo
__device__ float g_z [BATCH * 32 * 32 * 32];  // z hi
__device__ float g_zl[BATCH * 32 * 32 * 32];  // z lo
__device__ float g_q [BATCH * 32 * 32 * 32];  // quantized latent (tf32-rounded)
__device__ float g_lpart[2048];               // per-block loss partials
__device__ float g_wb [131072];               // prepped weights hi, group-major
__device__ float g_wbl[131072];               // weights lo
__device__ float g_cbh[16384];                // codebook hi
__device__ float g_cbl[16384];                // codebook lo
__device__ float g_cn[512];                   // codebook norms (fp32)

// group-major layout: [grp][tap][cig(8)][co]   (conv2: [grp][plane][tap][cig][co])
#define OFF_C2  0        // conv2 : 4grp*4plane*4tap*8*64 = 32768
#define OFF_C3  32768    // conv3 : 8*9*8*64 = 36864
#define OFF_C4  69632    // conv4 : 8*1*8*32 = 2048
#define OFF_D1  71680    // dec1  : 4*9*8*64 = 18432
#define OFF_T1  90112    // deconv1: 4cls * (8*4*8*32) = 32768

// ------------------- tf32 helpers -------------------
__device__ __forceinline__ unsigned f2tf32(float x) {
    unsigned r;
    asm("cvt.rna.tf32.f32 %0, %1;" : "=r"(r) : "f"(x));
    return r;
}

__device__ __forceinline__ void mma_tf32(float& c0, float& c1, float& c2, float& c3,
                                         unsigned a0, unsigned a1, unsigned a2, unsigned a3,
                                         unsigned b0, unsigned b1) {
    asm volatile("mma.sync.aligned.m16n8k8.row.col.f32.tf32.tf32.f32 "
                 "{%0,%1,%2,%3}, {%4,%5,%6,%7}, {%8,%9}, {%0,%1,%2,%3};"
                 : "+f"(c0), "+f"(c1), "+f"(c2), "+f"(c3)
                 : "r"(a0), "r"(a1), "r"(a2), "r"(a3), "r"(b0), "r"(b1));
}

__host__ __device__ constexpr int calc_pw(int h, int w) {
    int p = w;
    while (((h * p) & 31) != 8) p++;
    return p;
}

// ------------------- fused prep: weights hi/lo (group-major), codebook, norms -------------------
__global__ void k_prep_all(const float* __restrict__ ew2, const float* __restrict__ ew3,
                           const float* __restrict__ ew4, const float* __restrict__ dw1,
                           const float* __restrict__ tw1, const float* __restrict__ cb,
                           float* __restrict__ wbh, float* __restrict__ wbl,
                           float* __restrict__ cbh, float* __restrict__ cbl,
                           float* __restrict__ cn) {
    const int b = blockIdx.x, t = threadIdx.x;
    float v; int oidx;
    if (b < 128) {                       // conv2 parity-split: [grp4][plane4][tap4][cig8][co64]
        int i = b * 256 + t;
        int co = i & 63, r = i >> 6, cig = r & 7, r2 = r >> 3;
        int tap = r2 & 3, r3 = r2 >> 2, plane = r3 & 3, grp = r3 >> 2;
        int py = plane >> 1, px = plane & 1;
        int ty = tap >> 1, tx = tap & 1;
        int ky = (py == 0) ? (ty ? 3 : 1) : (ty ? 2 : 0);
        int kx = (px == 0) ? (tx ? 3 : 1) : (tx ? 2 : 0);
        int ci = grp * 8 + cig;
        v = ew2[(co * 32 + ci) * 16 + ky * 4 + kx]; oidx = OFF_C2 + i;
    } else if (b < 272) {                // conv3: [grp8][tap9][cig8][co64]
        int i = (b - 128) * 256 + t;
        int co = i & 63, r = i >> 6, cig = r & 7, r2 = r >> 3, tap = r2 % 9, grp = r2 / 9;
        int ci = grp * 8 + cig;
        v = ew3[(co * 64 + ci) * 9 + tap]; oidx = OFF_C3 + i;
    } else if (b < 280) {                // conv4: [grp8][cig8][co32]
        int i = (b - 272) * 256 + t;
        int co = i & 31, r = i >> 5, cig = r & 7, grp = r >> 3;
        int ci = grp * 8 + cig;
        v = ew4[co * 64 + ci]; oidx = OFF_C4 + i;
    } else if (b < 352) {                // dec1: [grp4][tap9][cig8][co64]
        int i = (b - 280) * 256 + t;
        int co = i & 63, r = i >> 6, cig = r & 7, r2 = r >> 3, tap = r2 % 9, grp = r2 / 9;
        int ci = grp * 8 + cig;
        v = dw1[(co * 32 + ci) * 9 + tap]; oidx = OFF_D1 + i;
    } else if (b < 480) {                // deconv1: [cls4][grp8][tap4][cig8][co32]
        int i = (b - 352) * 256 + t;
        int co = i & 31, r = i >> 5, cig = r & 7, r2 = r >> 3, tap = r2 & 3, r3 = r2 >> 2;
        int grp = r3 & 7, cls = r3 >> 3;
        int py = cls >> 1, px = cls & 1;
        int ty = tap >> 1, tx = tap & 1;
        int ky = ty ? 3 - py : 1 - py;
        int kx = tx ? 3 - px : 1 - px;
        int ci = grp * 8 + cig;
        v = tw1[(ci * 32 + co) * 16 + ky * 4 + kx]; oidx = OFF_T1 + i;
    } else if (b < 544) {                // codebook hi/lo
        int i = (b - 480) * 256 + t;
        float cv = cb[i];
        unsigned hi = f2tf32(cv);
        cbh[i] = __uint_as_float(hi);
        cbl[i] = __uint_as_float(f2tf32(cv - __uint_as_float(hi)));
        return;
    } else {                             // norms
        int k = (b - 544) * 256 + t;
        if (k < 512) {
            float s = 0.f;
            const float* c = cb + k * 32;
            #pragma unroll
            for (int d = 0; d < 32; d++) s = fmaf(c[d], c[d], s);
            cn[k] = s;
        }
        return;
    }
    unsigned hi = f2tf32(v);
    wbh[oidx] = __uint_as_float(hi);
    wbl[oidx] = __uint_as_float(f2tf32(v - __uint_as_float(hi)));
}

// ------------------- tf32 implicit-GEMM with halo-tile smem staging -------------------
// M-tile 256 (8 warps x 2 m16). CS: COUT split across blockIdx.y (smaller acc state ->
// MINB blocks/SM). Per subgroup: stage halo + B chunk; one barrier pair; barrier-free
// LDS-fed tap loop. PSPLIT: stride-2 conv as 4 stride-1 2x2 convs on parity planes.
// OUTM: 0 fp32, 1 tf32-rounded, 2 hi/lo dual.
template<int CIN, int HIN, int COUT, int S, int K, int P, int NTAPS,
         bool DECONV, bool PSPLIT, int OS, int W, bool X3, bool RELU, int OUTM,
         int CS, int MINB>
__global__ void __launch_bounds__(256, MINB)
k_igemm(const float* __restrict__ in, const float* __restrict__ inl,
        const float* __restrict__ wbh, const float* __restrict__ wbl,
        const float* __restrict__ bias,
        float* __restrict__ out, float* __restrict__ outl) {
    constexpr int G8 = CIN / 8;
    constexpr int NG = PSPLIT ? G8 * 4 : G8;
    constexpr int COUTH = COUT / CS;
    constexpr int NT = COUTH / 8;
    constexpr int HH = PSPLIT ? 9  : 7 * S + (DECONV ? 2 : K);
    constexpr int HW = PSPLIT ? 33 : 31 * S + (DECONV ? 2 : K);
    constexpr int PW = calc_pw(HH, HW);
    constexpr int CHS = HH * PW;
    constexpr int BP = COUTH + 8;
    constexpr int ASZ = 8 * CHS;
    constexpr int BSZ = NTAPS * 8 * BP;
    constexpr int AS = PSPLIT ? 1 : S;

    extern __shared__ float sm[];
    float* Ah = sm;
    float* Al = Ah + ASZ;
    float* Bh = Ah + (X3 ? 2 : 1) * ASZ;
    float* Bl = Bh + BSZ;

    const int t = threadIdx.x, lane = t & 31, wrp = t >> 5;
    const int g = lane >> 2, tg = lane & 3;
    const int n = blockIdx.z;
    const int m0 = blockIdx.x * 256;
    const int r0 = blockIdx.x * 8;

    int cpy = 0, cpx = 0, cls = 0, coH0 = 0;
    if (DECONV) { cls = blockIdx.y; cpy = cls >> 1; cpx = cls & 1; }
    else if (CS > 1) { coH0 = blockIdx.y * COUTH; }

    int aoff[4];
    #pragma unroll
    for (int q = 0; q < 4; q++) {
        int ml = wrp * 32 + (q >> 1) * 16 + g + (q & 1) * 8;
        int oyl = ml >> 5, ox = ml & 31;
        aoff[q] = tg * CHS + (oyl * AS) * PW + ox * AS;
    }
    const int btg = tg * BP, btg4 = (tg + 4) * BP;

    float acc[NT][2][4];
    #pragma unroll
    for (int i = 0; i < NT; i++)
        #pragma unroll
        for (int mt = 0; mt < 2; mt++)
            #pragma unroll
            for (int j = 0; j < 4; j++) acc[i][mt][j] = 0.f;

    for (int sg = 0; sg < NG; sg++) {
        const int grp   = PSPLIT ? (sg >> 2) : sg;
        const int plane = PSPLIT ? (sg & 3) : 0;
        const int DYMIN = PSPLIT ? -(plane >> 1) : (DECONV ? cpy - 1 : -P);
        const int DXMIN = PSPLIT ? -(plane & 1)  : (DECONV ? cpx - 1 : -P);
        const int ci0 = grp * 8;
        __syncthreads();
        // ---- stage A halo ----
        for (int i = t; i < 8 * HH * HW; i += 256) {
            int ch = i / (HH * HW), rem = i % (HH * HW);
            int rr = rem / HW, cc = rem % HW;
            int iy = (PSPLIT ? r0 : r0 * S) + DYMIN + rr;
            int ix = DXMIN + cc;
            bool ok = (unsigned)iy < (unsigned)HIN && (unsigned)ix < (unsigned)HIN;
            long gi;
            if (PSPLIT)
                gi = (((long)n * CIN + ci0 + ch) * 4 + plane) * (HIN * HIN)
                   + (long)iy * HIN + ix;
            else
                gi = ((long)n * CIN + ci0 + ch) * (HIN * HIN) + (long)iy * HIN + ix;
            int si = ch * CHS + rr * PW + cc;
            Ah[si] = ok ? __ldg(in + gi) : 0.f;
            if (X3) Al[si] = ok ? __ldg(inl + gi) : 0.f;
        }
        // ---- stage B (all taps of this subgroup, this co-half) ----
        {
            const long wo = (DECONV ? (long)cls * NG * NTAPS * 8 * COUT : 0)
                          + (long)sg * NTAPS * 8 * COUT;
            for (int i = t; i < NTAPS * 8 * COUTH; i += 256) {
                int tap = i / (8 * COUTH), rem = i % (8 * COUTH);
                int k = rem / COUTH, c = rem % COUTH;
                int si = tap * 8 * BP + k * BP + c;
                long wi = wo + (long)(tap * 8 + k) * COUT + coH0 + c;
                Bh[si] = wbh[wi];
                if (X3) Bl[si] = wbl[wi];
            }
        }
        __syncthreads();

        // ---- barrier-free tap loop ----
        for (int tap = 0; tap < NTAPS; tap++) {
            int ty, tx;
            if (PSPLIT)      { ty = tap >> 1;                          tx = tap & 1; }
            else if (DECONV) { ty = (cpy - (tap >> 1)) - DYMIN;        tx = (cpx - (tap & 1)) - DXMIN; }
            else             { ty = tap / K;                           tx = tap % K; }
            const int toff = ty * PW + tx;

            unsigned ah[2][4], al[2][4];
            #pragma unroll
            for (int q = 0; q < 4; q++) {
                int si = aoff[q] + toff;
                int mt = q >> 1, h = q & 1;
                ah[mt][h]     = __float_as_uint(Ah[si]);
                ah[mt][2 + h] = __float_as_uint(Ah[si + 4 * CHS]);
                if (X3) {
                    al[mt][h]     = __float_as_uint(Al[si]);
                    al[mt][2 + h] = __float_as_uint(Al[si + 4 * CHS]);
                }
            }

            const float* Bth = Bh + tap * 8 * BP;
            const float* Btl = Bl + tap * 8 * BP;
            #pragma unroll
            for (int nt = 0; nt < NT; nt++) {
                unsigned bh0 = __float_as_uint(Bth[btg + nt * 8 + g]);
                unsigned bh1 = __float_as_uint(Bth[btg4 + nt * 8 + g]);
                unsigned bl0 = 0, bl1 = 0;
                if (X3) {
                    bl0 = __float_as_uint(Btl[btg + nt * 8 + g]);
                    bl1 = __float_as_uint(Btl[btg4 + nt * 8 + g]);
                }
                #pragma unroll
                for (int mt = 0; mt < 2; mt++) {
                    if (X3) {
                        mma_tf32(acc[nt][mt][0], acc[nt][mt][1], acc[nt][mt][2], acc[nt][mt][3],
                                 al[mt][0], al[mt][1], al[mt][2], al[mt][3], bh0, bh1);
                        mma_tf32(acc[nt][mt][0], acc[nt][mt][1], acc[nt][mt][2], acc[nt][mt][3],
                                 ah[mt][0], ah[mt][1], ah[mt][2], ah[mt][3], bl0, bl1);
                    }
                    mma_tf32(acc[nt][mt][0], acc[nt][mt][1], acc[nt][mt][2], acc[nt][mt][3],
                             ah[mt][0], ah[mt][1], ah[mt][2], ah[mt][3], bh0, bh1);
                }
            }
        }
    }

    // ---- epilogue: direct strided stores ----
    int eoy[4], eox[4];
    #pragma unroll
    for (int q = 0; q < 4; q++) {
        int m = m0 + wrp * 32 + (q >> 1) * 16 + ((q & 1) ? g + 8 : g);
        eoy[q] = (m >> 5) * OS + cpy;
        eox[q] = (m & 31) * OS + cpx;
    }
    #pragma unroll
    for (int nt = 0; nt < NT; nt++) {
        int co = coH0 + nt * 8 + 2 * tg;
        float b0 = __ldg(bias + co), b1 = __ldg(bias + co + 1);
        #pragma unroll
        for (int mt = 0; mt < 2; mt++) {
            #pragma unroll
            for (int hh = 0; hh < 2; hh++) {
                int qd = mt * 2 + hh;
                float v0 = acc[nt][mt][hh * 2 + 0] + b0;
                float v1 = acc[nt][mt][hh * 2 + 1] + b1;
                if (RELU) { v0 = fmaxf(v0, 0.f); v1 = fmaxf(v1, 0.f); }
                long ob = (((long)n * COUT + co) * W + eoy[qd]) * W + eox[qd];
                long ob1 = ob + (long)W * W;
                if (OUTM == 0) {
                    out[ob] = v0; out[ob1] = v1;
                } else if (OUTM == 1) {
                    out[ob]  = __uint_as_float(f2tf32(v0));
                    out[ob1] = __uint_as_float(f2tf32(v1));
                } else {
                    unsigned h0 = f2tf32(v0), h1 = f2tf32(v1);
                    out[ob]  = __uint_as_float(h0);
                    out[ob1] = __uint_as_float(h1);
                    outl[ob]  = __uint_as_float(f2tf32(v0 - __uint_as_float(h0)));
                    outl[ob1] = __uint_as_float(f2tf32(v1 - __uint_as_float(h1)));
                }
            }
        }
    }
}

// ------------------- conv1 (scalar, CIN=1), parity-split dual tf32 output -------------------
template<int CIN, int HIN, int K, int S, int P, int COUT, int CT, int ST>
__global__ void k_conv1(const float* __restrict__ in, const float* __restrict__ w,
                        const float* __restrict__ bias,
                        float* __restrict__ out, float* __restrict__ outl) {
    constexpr int HOUT = (HIN + 2 * P - K) / S + 1;
    constexpr int KK = K * K;
    __shared__ float sw[CT * CIN * KK];
    const int co0 = blockIdx.y * CT;
    const int n   = blockIdx.z;
    const int t   = threadIdx.x;
    for (int i = t; i < CT * CIN * KK; i += 256) {
        int c = i / (CIN * KK), rest = i % (CIN * KK);
        sw[i] = w[(co0 + c) * CIN * KK + rest];
    }
    __syncthreads();

    const int p0  = (blockIdx.x * 256 + t) * ST;
    const int oy  = p0 / HOUT;
    const int ox0 = p0 % HOUT;

    float acc[CT][ST];
    #pragma unroll
    for (int c = 0; c < CT; c++) {
        float bv = bias[co0 + c];
        #pragma unroll
        for (int s = 0; s < ST; s++) acc[c][s] = bv;
    }

    const float* ib = in + (long)n * CIN * HIN * HIN;
    for (int ci = 0; ci < CIN; ci++) {
        const float* ic = ib + ci * HIN * HIN;
        #pragma unroll
        for (int ky = 0; ky < K; ky++) {
            int iy = oy * S - P + ky;
            if ((unsigned)iy < (unsigned)HIN) {
                const float* row = ic + iy * HIN;
                #pragma unroll
                for (int kx = 0; kx < K; kx++) {
                    float xv[ST];
                    #pragma unroll
                    for (int s = 0; s < ST; s++) {
                        int ix = (ox0 + s) * S - P + kx;
                        xv[s] = ((unsigned)ix < (unsigned)HIN) ? row[ix] : 0.f;
                    }
                    #pragma unroll
                    for (int c = 0; c < CT; c++) {
                        float wv = sw[(c * CIN + ci) * KK + ky * K + kx];
                        #pragma unroll
                        for (int s = 0; s < ST; s++)
                            acc[c][s] = fmaf(xv[s], wv, acc[c][s]);
                    }
                }
            }
        }
    }

    const int py = oy & 1, u = oy >> 1;
    #pragma unroll
    for (int c = 0; c < CT; c++) {
        #pragma unroll
        for (int s = 0; s < ST; s++) {
            int ox = ox0 + s;
            int plane = py * 2 + (ox & 1);
            long ob = ((((long)n * COUT + co0 + c) * 4 + plane) * 32 + u) * 32 + (ox >> 1);
            float v = fmaxf(acc[c][s], 0.f);
            unsigned hi = f2tf32(v);
            out[ob]  = __uint_as_float(hi);
            outl[ob] = __uint_as_float(f2tf32(v - __uint_as_float(hi)));
        }
    }
}

// ------------------- deconv2: [256,32,64,64] -> [256,1,128,128], sigmoid -------------------
__global__ void k_deconv2(const float* __restrict__ in, const float* __restrict__ w,
                          const float* __restrict__ bias, float* __restrict__ out) {
    __shared__ float sw[512];
    const int t = threadIdx.x;
    const int n = blockIdx.z;
    for (int i = t; i < 512; i += 256) sw[i] = w[i];
    __syncthreads();

    const int ti = blockIdx.x * 256 + t;
    const int ty = ti >> 4, tx = ti & 15;
    const float bv = __ldg(bias);

    float acc[4][8];
    #pragma unroll
    for (int r = 0; r < 4; r++)
        #pragma unroll
        for (int c = 0; c < 8; c++) acc[r][c] = 0.f;

    const float* ib = in + (long)n * 32 * 4096;
    for (int ci = 0; ci < 32; ci++) {
        const float* ic = ib + ci * 4096;
        float xv[4][6];
        #pragma unroll
        for (int rr = 0; rr < 4; rr++) {
            int iy = 2 * ty - 1 + rr;
            bool vy = (unsigned)iy < 64u;
            const float* row = ic + iy * 64;
            int c0 = 4 * tx - 1;
            xv[rr][0] = (vy && c0 >= 0) ? row[c0] : 0.f;
            if (vy) {
                float4 m4 = *(const float4*)(row + 4 * tx);
                xv[rr][1] = m4.x; xv[rr][2] = m4.y; xv[rr][3] = m4.z; xv[rr][4] = m4.w;
            } else {
                xv[rr][1] = xv[rr][2] = xv[rr][3] = xv[rr][4] = 0.f;
            }
            int c5 = 4 * tx + 4;
            xv[rr][5] = (vy && c5 < 64) ? row[c5] : 0.f;
        }
        float wr[16];
        #pragma unroll
        for (int k = 0; k < 16; k++) wr[k] = sw[ci * 16 + k];
        #pragma unroll
        for (int r = 0; r < 4; r++) {
            const int pyy = r & 1;
            const int rowA = (r >> 1) + pyy + 1, rowB = rowA - 1;
            #pragma unroll
            for (int c = 0; c < 8; c++) {
                const int pxx = c & 1;
                const int colA = (c >> 1) + pxx + 1, colB = colA - 1;
                float a = acc[r][c];
                a = fmaf(xv[rowA][colA], wr[(1 - pyy) * 4 + (1 - pxx)], a);
                a = fmaf(xv[rowA][colB], wr[(1 - pyy) * 4 + (3 - pxx)], a);
                a = fmaf(xv[rowB][colA], wr[(3 - pyy) * 4 + (1 - pxx)], a);
                a = fmaf(xv[rowB][colB], wr[(3 - pyy) * 4 + (3 - pxx)], a);
                acc[r][c] = a;
            }
        }
    }

    float* ob = out + (long)n * 16384;
    #pragma unroll
    for (int r = 0; r < 4; r++) {
        int oy = 4 * ty + r;
        float v[8];
        #pragma unroll
        for (int c = 0; c < 8; c++)
            v[c] = 1.f / (1.f + expf(-(acc[r][c] + bv)));
        *(float4*)(ob + oy * 128 + 8 * tx)     = make_float4(v[0], v[1], v[2], v[3]);
        *(float4*)(ob + oy * 128 + 8 * tx + 4) = make_float4(v[4], v[5], v[6], v[7]);
    }
}

// ------------------- VQ on tensor cores (3xTF32, pre-split operands) -------------------
__global__ void k_vq_tc(const float* __restrict__ zh, const float* __restrict__ zl,
                        const float* __restrict__ cb, const float* __restrict__ cbh,
                        const float* __restrict__ cbl, const float* __restrict__ cn,
                        float* __restrict__ q, float* __restrict__ lpart) {
    __shared__ unsigned As[2][32][136];
    __shared__ unsigned Bs[2][32][40];
    __shared__ float scn[32];
    __shared__ int sidx[128];
    __shared__ float red[256];
    const int t = threadIdx.x, lane = t & 31, wrp = t >> 5;
    const int g = lane >> 2, tg = lane & 3;
    const int n  = blockIdx.x >> 3;
    const int p0 = (blockIdx.x & 7) * 128;
    const int mw = wrp * 16;

    for (int i = t; i < 4096; i += 256) {
        int d = i >> 7, m = i & 127;
        long zi = ((long)n * 32 + d) * 1024 + p0 + m;
        As[0][d][m] = __float_as_uint(zh[zi]);
        As[1][d][m] = __float_as_uint(zl[zi]);
    }
    __syncthreads();

    unsigned ah[4][4], al[4][4];
    #pragma unroll
    for (int s = 0; s < 4; s++) {
        ah[s][0] = As[0][s * 8 + tg][mw + g];     ah[s][1] = As[0][s * 8 + tg][mw + g + 8];
        ah[s][2] = As[0][s * 8 + tg + 4][mw + g]; ah[s][3] = As[0][s * 8 + tg + 4][mw + g + 8];
        al[s][0] = As[1][s * 8 + tg][mw + g];     al[s][1] = As[1][s * 8 + tg][mw + g + 8];
        al[s][2] = As[1][s * 8 + tg + 4][mw + g]; al[s][3] = As[1][s * 8 + tg + 4][mw + g + 8];
    }

    float best0 = 3.4e38f, best1 = 3.4e38f;
    int bidx0 = 0, bidx1 = 0;

    for (int ch = 0; ch < 16; ch++) {
        const int k0 = ch * 32;
        __syncthreads();
        for (int i = t; i < 1024; i += 256) {
            int d = i & 31, kk = i >> 5;
            Bs[0][d][kk] = __float_as_uint(cbh[(k0 + kk) * 32 + d]);
            Bs[1][d][kk] = __float_as_uint(cbl[(k0 + kk) * 32 + d]);
        }
        if (t < 32) scn[t] = cn[k0 + t];
        __syncthreads();

        #pragma unroll
        for (int nt = 0; nt < 4; nt++) {
            float a0 = 0.f, a1 = 0.f, a2 = 0.f, a3 = 0.f;
            #pragma unroll
            for (int s = 0; s < 4; s++) {
                unsigned bh0 = Bs[0][s * 8 + tg][nt * 8 + g], bh1 = Bs[0][s * 8 + tg + 4][nt * 8 + g];
                unsigned bl0 = Bs[1][s * 8 + tg][nt * 8 + g], bl1 = Bs[1][s * 8 + tg + 4][nt * 8 + g];
                mma_tf32(a0, a1, a2, a3, al[s][0], al[s][1], al[s][2], al[s][3], bh0, bh1);
                mma_tf32(a0, a1, a2, a3, ah[s][0], ah[s][1], ah[s][2], ah[s][3], bl0, bl1);
                mma_tf32(a0, a1, a2, a3, ah[s][0], ah[s][1], ah[s][2], ah[s][3], bh0, bh1);
            }
            int kc0 = k0 + nt * 8 + 2 * tg, kc1 = kc0 + 1;
            float c0 = scn[nt * 8 + 2 * tg], c1 = scn[nt * 8 + 2 * tg + 1];
            float d00 = fmaf(-2.f, a0, c0), d01 = fmaf(-2.f, a1, c1);
            float d10 = fmaf(-2.f, a2, c0), d11 = fmaf(-2.f, a3, c1);
            if (d00 < best0) { best0 = d00; bidx0 = kc0; }
            if (d01 < best0) { best0 = d01; bidx0 = kc1; }
            if (d10 < best1) { best1 = d10; bidx1 = kc0; }
            if (d11 < best1) { best1 = d11; bidx1 = kc1; }
        }
    }

    #pragma unroll
    for (int off = 1; off < 4; off <<= 1) {
        float ob; int oi;
        ob = __shfl_down_sync(0xffffffffu, best0, off, 4);
        oi = __shfl_down_sync(0xffffffffu, bidx0, off, 4);
        if (ob < best0 || (ob == best0 && oi < bidx0)) { best0 = ob; bidx0 = oi; }
        ob = __shfl_down_sync(0xffffffffu, best1, off, 4);
        oi = __shfl_down_sync(0xffffffffu, bidx1, off, 4);
        if (ob < best1 || (ob == best1 && oi < bidx1)) { best1 = ob; bidx1 = oi; }
    }
    if (tg == 0) { sidx[mw + g] = bidx0; sidx[mw + g + 8] = bidx1; }
    __syncthreads();

    float lsum = 0.f;
    for (int i = t; i < 4096; i += 256) {
        int d = i >> 7, m = i & 127;
        long zi = ((long)n * 32 + d) * 1024 + p0 + m;
        float qv = __ldg(cb + sidx[m] * 32 + d);
        float zv = zh[zi] + zl[zi];
        q[zi] = __uint_as_float(f2tf32(qv));
        float e = qv - zv;
        lsum = fmaf(e, e, lsum);
    }
    red[t] = lsum;
    __syncthreads();
    for (int s = 128; s > 0; s >>= 1) {
        if (t < s) red[t] += red[t + s];
        __syncthreads();
    }
    if (t == 0) lpart[blockIdx.x] = red[0];
}

// deterministic fixed-order final reduction: vq_loss = 1.26 * mean
__global__ void k_loss(const float* __restrict__ lpart, float* __restrict__ out,
                       int out_size) {
    __shared__ float red[256];
    const int t = threadIdx.x;
    float s = 0.f;
    #pragma unroll
    for (int j = 0; j < 8; j++) s += lpart[t + 256 * j];
    red[t] = s;
    __syncthreads();
    for (int st = 128; st > 0; st >>= 1) {
        if (t < st) red[t] += red[t + st];
        __syncthreads();
    }
    if (t == 0) out[out_size - 1] = 1.26f * red[0] / 8388608.0f;
}

// ------------------- launch -------------------
extern "C" void kernel_launch(void* const* d_in, const int* in_sizes, int n_in,
                              void* d_out, int out_size) {
    const float* x   = (const float*)d_in[0];
    const float* ew1 = (const float*)d_in[1];  const float* eb1 = (const float*)d_in[2];
    const float* ew2 = (const float*)d_in[3];  const float* eb2 = (const float*)d_in[4];
    const float* ew3 = (const float*)d_in[5];  const float* eb3 = (const float*)d_in[6];
    const float* ew4 = (const float*)d_in[7];  const float* eb4 = (const float*)d_in[8];
    const float* cb  = (const float*)d_in[9];
    const float* dw1 = (const float*)d_in[10]; const float* db1 = (const float*)d_in[11];
    const float* tw1 = (const float*)d_in[12]; const float* tb1 = (const float*)d_in[13];
    const float* tw2 = (const float*)d_in[14]; const float* tb2 = (const float*)d_in[15];
    float* out = (float*)d_out;

    float *pa, *pal, *pb, *pbl, *pc, *pcl, *pz, *pzl, *pq, *pl;
    float *pwb, *pwbl, *pcbh, *pcbl, *pcn;
    cudaGetSymbolAddress((void**)&pa,  g_a);   cudaGetSymbolAddress((void**)&pal, g_al);
    cudaGetSymbolAddress((void**)&pb,  g_b);   cudaGetSymbolAddress((void**)&pbl, g_bl);
    cudaGetSymbolAddress((void**)&pc,  g_c);   cudaGetSymbolAddress((void**)&pcl, g_cl);
    cudaGetSymbolAddress((void**)&pz,  g_z);   cudaGetSymbolAddress((void**)&pzl, g_zl);
    cudaGetSymbolAddress((void**)&pq,  g_q);
    cudaGetSymbolAddress((void**)&pl,  g_lpart);
    cudaGetSymbolAddress((void**)&pwb, g_wb);  cudaGetSymbolAddress((void**)&pwbl, g_wbl);
    cudaGetSymbolAddress((void**)&pcbh, g_cbh); cudaGetSymbolAddress((void**)&pcbl, g_cbl);
    cudaGetSymbolAddress((void**)&pcn, g_cn);

    // kernel instances: CS-split for the big X3 convs -> 3 blocks/SM
    auto kc2 = k_igemm<32, 32, 64, 1, 2, 0, 4, false, true,  1, 32, true,  true,  2, 2, 3>;
    auto kc3 = k_igemm<64, 32, 64, 1, 3, 1, 9, false, false, 1, 32, true,  true,  2, 2, 3>;
    auto kc4 = k_igemm<64, 32, 32, 1, 1, 0, 1, false, false, 1, 32, true,  false, 2, 1, 3>;
    auto kd1 = k_igemm<32, 32, 64, 1, 3, 1, 9, false, false, 1, 32, false, true,  1, 1, 2>;
    auto kt1 = k_igemm<64, 32, 32, 1, 1, 0, 4, true,  false, 2, 64, false, true,  0, 1, 2>;
    const int SM_C2 = 33280, SM_C3 = 46080, SM_C4 = 19456, SM_D1 = 32256, SM_T1 = 16640;
    cudaFuncSetAttribute(kc2, cudaFuncAttributeMaxDynamicSharedMemorySize, SM_C2);
    cudaFuncSetAttribute(kc3, cudaFuncAttributeMaxDynamicSharedMemorySize, SM_C3);
    cudaFuncSetAttribute(kc4, cudaFuncAttributeMaxDynamicSharedMemorySize, SM_C4);
    cudaFuncSetAttribute(kd1, cudaFuncAttributeMaxDynamicSharedMemorySize, SM_D1);
    cudaFuncSetAttribute(kt1, cudaFuncAttributeMaxDynamicSharedMemorySize, SM_T1);

    k_prep_all<<<546, 256>>>(ew2, ew3, ew4, dw1, tw1, cb, pwb, pwbl, pcbh, pcbl, pcn);

    // Encoder (conv1 writes parity-split planes for conv2)
    k_conv1<1, 128, 4, 2, 1, 32, 8, 4><<<dim3(4, 4, BATCH), 256>>>(x, ew1, eb1, pa, pal);
    kc2<<<dim3(4, 2, BATCH), 256, SM_C2>>>(pa, pal, pwb + OFF_C2, pwbl + OFF_C2, eb2, pb, pbl);
    kc3<<<dim3(4, 2, BATCH), 256, SM_C3>>>(pb, pbl, pwb + OFF_C3, pwbl + OFF_C3, eb3, pc, pcl);
    kc4<<<dim3(4, 1, BATCH), 256, SM_C4>>>(pc, pcl, pwb + OFF_C4, pwbl + OFF_C4, eb4, pz, pzl);

    // VQ (3xTF32, pre-split)
    k_vq_tc<<<2048, 256>>>(pz, pzl, cb, pcbh, pcbl, pcn, pq, pl);

    // Decoder
    kd1<<<dim3(4, 1, BATCH), 256, SM_D1>>>(pq, pq, pwb + OFF_D1, pwbl + OFF_D1, db1, pc, pc);
    kt1<<<dim3(4, 4, BATCH), 256, SM_T1>>>(pc, pc, pwb + OFF_T1, pwbl + OFF_T1, tb1, pa, pa);
    k_deconv2<<<dim3(2, 1, BATCH), 256>>>(pa, tw2, tb2, out);

    k_loss<<<1, 256>>>(pl, out, out_size);
}

// round 12
// speedup vs baseline: 1.4157x; 1.3583x over previous
#include <cuda_runtime.h>
#include <math.h>

#define BATCH 256

// ------------------- scratch (alloc-free rule: device globals) -------------------
__device__ float g_a [BATCH * 32 * 64 * 64];  // conv1 out (parity-split, tf32) / deconv1 out
__device__ float g_b [BATCH * 64 * 32 * 32];  // conv2 out (tf32)
__device__ float g_c [BATCH * 64 * 32 * 32];  // conv3 out (tf32) / dec1 out (tf32)
__device__ float g_z [BATCH * 32 * 32 * 32];  // z hi
__device__ float g_zl[BATCH * 32 * 32 * 32];  // z lo
__device__ float g_q [BATCH * 32 * 32 * 32];  // quantized latent (tf32-rounded)
__device__ float g_lpart[2048];               // per-block loss partials
__device__ float g_wb [131072];               // prepped weights hi, group-major
__device__ float g_wbl[131072];               // weights lo (VQ-era; kept, mostly unused)
__device__ float g_cbh[16384];                // codebook hi
__device__ float g_cbl[16384];                // codebook lo
__device__ float g_cn[512];                   // codebook norms (fp32)

// group-major layout: [grp][tap][cig(8)][co]   (conv2: [grp][plane][tap][cig][co])
#define OFF_C2  0        // conv2 : 4grp*4plane*4tap*8*64 = 32768
#define OFF_C3  32768    // conv3 : 8*9*8*64 = 36864
#define OFF_C4  69632    // conv4 : 8*1*8*32 = 2048
#define OFF_D1  71680    // dec1  : 4*9*8*64 = 18432
#define OFF_T1  90112    // deconv1: 4cls * (8*4*8*32) = 32768

// ------------------- tf32 helpers -------------------
__device__ __forceinline__ unsigned f2tf32(float x) {
    unsigned r;
    asm("cvt.rna.tf32.f32 %0, %1;" : "=r"(r) : "f"(x));
    return r;
}

__device__ __forceinline__ void mma_tf32(float& c0, float& c1, float& c2, float& c3,
                                         unsigned a0, unsigned a1, unsigned a2, unsigned a3,
                                         unsigned b0, unsigned b1) {
    asm volatile("mma.sync.aligned.m16n8k8.row.col.f32.tf32.tf32.f32 "
                 "{%0,%1,%2,%3}, {%4,%5,%6,%7}, {%8,%9}, {%0,%1,%2,%3};"
                 : "+f"(c0), "+f"(c1), "+f"(c2), "+f"(c3)
                 : "r"(a0), "r"(a1), "r"(a2), "r"(a3), "r"(b0), "r"(b1));
}

__host__ __device__ constexpr int calc_pw(int h, int w) {
    int p = w;
    while (((h * p) & 31) != 8) p++;
    return p;
}

// ------------------- fused prep: weights hi/lo (group-major), codebook, norms -------------------
__global__ void k_prep_all(const float* __restrict__ ew2, const float* __restrict__ ew3,
                           const float* __restrict__ ew4, const float* __restrict__ dw1,
                           const float* __restrict__ tw1, const float* __restrict__ cb,
                           float* __restrict__ wbh, float* __restrict__ wbl,
                           float* __restrict__ cbh, float* __restrict__ cbl,
                           float* __restrict__ cn) {
    const int b = blockIdx.x, t = threadIdx.x;
    float v; int oidx;
    if (b < 128) {                       // conv2 parity-split: [grp4][plane4][tap4][cig8][co64]
        int i = b * 256 + t;
        int co = i & 63, r = i >> 6, cig = r & 7, r2 = r >> 3;
        int tap = r2 & 3, r3 = r2 >> 2, plane = r3 & 3, grp = r3 >> 2;
        int py = plane >> 1, px = plane & 1;
        int ty = tap >> 1, tx = tap & 1;
        int ky = (py == 0) ? (ty ? 3 : 1) : (ty ? 2 : 0);
        int kx = (px == 0) ? (tx ? 3 : 1) : (tx ? 2 : 0);
        int ci = grp * 8 + cig;
        v = ew2[(co * 32 + ci) * 16 + ky * 4 + kx]; oidx = OFF_C2 + i;
    } else if (b < 272) {                // conv3: [grp8][tap9][cig8][co64]
        int i = (b - 128) * 256 + t;
        int co = i & 63, r = i >> 6, cig = r & 7, r2 = r >> 3, tap = r2 % 9, grp = r2 / 9;
        int ci = grp * 8 + cig;
        v = ew3[(co * 64 + ci) * 9 + tap]; oidx = OFF_C3 + i;
    } else if (b < 280) {                // conv4: [grp8][cig8][co32]
        int i = (b - 272) * 256 + t;
        int co = i & 31, r = i >> 5, cig = r & 7, grp = r >> 3;
        int ci = grp * 8 + cig;
        v = ew4[co * 64 + ci]; oidx = OFF_C4 + i;
    } else if (b < 352) {                // dec1: [grp4][tap9][cig8][co64]
        int i = (b - 280) * 256 + t;
        int co = i & 63, r = i >> 6, cig = r & 7, r2 = r >> 3, tap = r2 % 9, grp = r2 / 9;
        int ci = grp * 8 + cig;
        v = dw1[(co * 32 + ci) * 9 + tap]; oidx = OFF_D1 + i;
    } else if (b < 480) {                // deconv1: [cls4][grp8][tap4][cig8][co32]
        int i = (b - 352) * 256 + t;
        int co = i & 31, r = i >> 5, cig = r & 7, r2 = r >> 3, tap = r2 & 3, r3 = r2 >> 2;
        int grp = r3 & 7, cls = r3 >> 3;
        int py = cls >> 1, px = cls & 1;
        int ty = tap >> 1, tx = tap & 1;
        int ky = ty ? 3 - py : 1 - py;
        int kx = tx ? 3 - px : 1 - px;
        int ci = grp * 8 + cig;
        v = tw1[(ci * 32 + co) * 16 + ky * 4 + kx]; oidx = OFF_T1 + i;
    } else if (b < 544) {                // codebook hi/lo
        int i = (b - 480) * 256 + t;
        float cv = cb[i];
        unsigned hi = f2tf32(cv);
        cbh[i] = __uint_as_float(hi);
        cbl[i] = __uint_as_float(f2tf32(cv - __uint_as_float(hi)));
        return;
    } else {                             // norms
        int k = (b - 544) * 256 + t;
        if (k < 512) {
            float s = 0.f;
            const float* c = cb + k * 32;
            #pragma unroll
            for (int d = 0; d < 32; d++) s = fmaf(c[d], c[d], s);
            cn[k] = s;
        }
        return;
    }
    unsigned hi = f2tf32(v);
    wbh[oidx] = __uint_as_float(hi);
    wbl[oidx] = __uint_as_float(f2tf32(v - __uint_as_float(hi)));
}

// ------------------- tf32 implicit-GEMM with halo-tile smem staging -------------------
// M-tile 256 (8 warps x 2 m16). Per subgroup: stage halo + all-tap B chunk; one
// barrier pair; barrier-free LDS-fed tap loop. PSPLIT: stride-2 conv as 4 stride-1
// 2x2 convs on parity planes. X3: 3xTF32 hi/lo (only if inputs pre-split).
// OUTM: 0 fp32, 1 tf32-rounded, 2 hi/lo dual (for VQ).
template<int CIN, int HIN, int COUT, int S, int K, int P, int NTAPS,
         bool DECONV, bool PSPLIT, int OS, int W, bool X3, bool RELU, int OUTM>
__global__ void __launch_bounds__(256, 2)
k_igemm(const float* __restrict__ in, const float* __restrict__ inl,
        const float* __restrict__ wbh, const float* __restrict__ wbl,
        const float* __restrict__ bias,
        float* __restrict__ out, float* __restrict__ outl) {
    constexpr int G8 = CIN / 8;
    constexpr int NG = PSPLIT ? G8 * 4 : G8;
    constexpr int NT = COUT / 8;
    constexpr int HH = PSPLIT ? 9  : 7 * S + (DECONV ? 2 : K);
    constexpr int HW = PSPLIT ? 33 : 31 * S + (DECONV ? 2 : K);
    constexpr int PW = calc_pw(HH, HW);
    constexpr int CHS = HH * PW;
    constexpr int BP = COUT + 8;
    constexpr int ASZ = 8 * CHS;
    constexpr int BSZ = NTAPS * 8 * BP;
    constexpr int AS = PSPLIT ? 1 : S;

    extern __shared__ float sm[];
    float* Ah = sm;
    float* Al = Ah + ASZ;
    float* Bh = Ah + (X3 ? 2 : 1) * ASZ;
    float* Bl = Bh + BSZ;

    const int t = threadIdx.x, lane = t & 31, wrp = t >> 5;
    const int g = lane >> 2, tg = lane & 3;
    const int n = blockIdx.z;
    const int m0 = blockIdx.x * 256;
    const int r0 = blockIdx.x * 8;

    int cpy = 0, cpx = 0, cls = 0;
    if (DECONV) { cls = blockIdx.y; cpy = cls >> 1; cpx = cls & 1; }

    int aoff[4];
    #pragma unroll
    for (int q = 0; q < 4; q++) {
        int ml = wrp * 32 + (q >> 1) * 16 + g + (q & 1) * 8;
        int oyl = ml >> 5, ox = ml & 31;
        aoff[q] = tg * CHS + (oyl * AS) * PW + ox * AS;
    }
    const int btg = tg * BP, btg4 = (tg + 4) * BP;

    float acc[NT][2][4];
    #pragma unroll
    for (int i = 0; i < NT; i++)
        #pragma unroll
        for (int mt = 0; mt < 2; mt++)
            #pragma unroll
            for (int j = 0; j < 4; j++) acc[i][mt][j] = 0.f;

    for (int sg = 0; sg < NG; sg++) {
        const int grp   = PSPLIT ? (sg >> 2) : sg;
        const int plane = PSPLIT ? (sg & 3) : 0;
        const int DYMIN = PSPLIT ? -(plane >> 1) : (DECONV ? cpy - 1 : -P);
        const int DXMIN = PSPLIT ? -(plane & 1)  : (DECONV ? cpx - 1 : -P);
        const int ci0 = grp * 8;
        __syncthreads();
        // ---- stage A halo ----
        for (int i = t; i < 8 * HH * HW; i += 256) {
            int ch = i / (HH * HW), rem = i % (HH * HW);
            int rr = rem / HW, cc = rem % HW;
            int iy = (PSPLIT ? r0 : r0 * S) + DYMIN + rr;
            int ix = DXMIN + cc;
            bool ok = (unsigned)iy < (unsigned)HIN && (unsigned)ix < (unsigned)HIN;
            long gi;
            if (PSPLIT)
                gi = (((long)n * CIN + ci0 + ch) * 4 + plane) * (HIN * HIN)
                   + (long)iy * HIN + ix;
            else
                gi = ((long)n * CIN + ci0 + ch) * (HIN * HIN) + (long)iy * HIN + ix;
            int si = ch * CHS + rr * PW + cc;
            Ah[si] = ok ? __ldg(in + gi) : 0.f;
            if (X3) Al[si] = ok ? __ldg(inl + gi) : 0.f;
        }
        // ---- stage B ----
        {
            const long wo = (DECONV ? (long)cls * NG * NTAPS * 8 * COUT : 0)
                          + (long)sg * NTAPS * 8 * COUT;
            for (int i = t; i < NTAPS * 8 * COUT; i += 256) {
                int tap = i / (8 * COUT), rem = i % (8 * COUT);
                int k = rem / COUT, co = rem % COUT;
                int si = tap * 8 * BP + k * BP + co;
                Bh[si] = wbh[wo + i];
                if (X3) Bl[si] = wbl[wo + i];
            }
        }
        __syncthreads();

        // ---- barrier-free tap loop ----
        for (int tap = 0; tap < NTAPS; tap++) {
            int ty, tx;
            if (PSPLIT)      { ty = tap >> 1;                          tx = tap & 1; }
            else if (DECONV) { ty = (cpy - (tap >> 1)) - DYMIN;        tx = (cpx - (tap & 1)) - DXMIN; }
            else             { ty = tap / K;                           tx = tap % K; }
            const int toff = ty * PW + tx;

            unsigned ah[2][4], al[2][4];
            #pragma unroll
            for (int q = 0; q < 4; q++) {
                int si = aoff[q] + toff;
                int mt = q >> 1, h = q & 1;
                ah[mt][h]     = __float_as_uint(Ah[si]);
                ah[mt][2 + h] = __float_as_uint(Ah[si + 4 * CHS]);
                if (X3) {
                    al[mt][h]     = __float_as_uint(Al[si]);
                    al[mt][2 + h] = __float_as_uint(Al[si + 4 * CHS]);
                }
            }

            const float* Bth = Bh + tap * 8 * BP;
            const float* Btl = Bl + tap * 8 * BP;
            #pragma unroll
            for (int nt = 0; nt < NT; nt++) {
                unsigned bh0 = __float_as_uint(Bth[btg + nt * 8 + g]);
                unsigned bh1 = __float_as_uint(Bth[btg4 + nt * 8 + g]);
                unsigned bl0 = 0, bl1 = 0;
                if (X3) {
                    bl0 = __float_as_uint(Btl[btg + nt * 8 + g]);
                    bl1 = __float_as_uint(Btl[btg4 + nt * 8 + g]);
                }
                #pragma unroll
                for (int mt = 0; mt < 2; mt++) {
                    if (X3) {
                        mma_tf32(acc[nt][mt][0], acc[nt][mt][1], acc[nt][mt][2], acc[nt][mt][3],
                                 al[mt][0], al[mt][1], al[mt][2], al[mt][3], bh0, bh1);
                        mma_tf32(acc[nt][mt][0], acc[nt][mt][1], acc[nt][mt][2], acc[nt][mt][3],
                                 ah[mt][0], ah[mt][1], ah[mt][2], ah[mt][3], bl0, bl1);
                    }
                    mma_tf32(acc[nt][mt][0], acc[nt][mt][1], acc[nt][mt][2], acc[nt][mt][3],
                             ah[mt][0], ah[mt][1], ah[mt][2], ah[mt][3], bh0, bh1);
                }
            }
        }
    }

    // ---- epilogue: direct strided stores ----
    int eoy[4], eox[4];
    #pragma unroll
    for (int q = 0; q < 4; q++) {
        int m = m0 + wrp * 32 + (q >> 1) * 16 + ((q & 1) ? g + 8 : g);
        eoy[q] = (m >> 5) * OS + cpy;
        eox[q] = (m & 31) * OS + cpx;
    }
    #pragma unroll
    for (int nt = 0; nt < NT; nt++) {
        int co = nt * 8 + 2 * tg;
        float b0 = __ldg(bias + co), b1 = __ldg(bias + co + 1);
        #pragma unroll
        for (int mt = 0; mt < 2; mt++) {
            #pragma unroll
            for (int hh = 0; hh < 2; hh++) {
                int qd = mt * 2 + hh;
                float v0 = acc[nt][mt][hh * 2 + 0] + b0;
                float v1 = acc[nt][mt][hh * 2 + 1] + b1;
                if (RELU) { v0 = fmaxf(v0, 0.f); v1 = fmaxf(v1, 0.f); }
                long ob = (((long)n * COUT + co) * W + eoy[qd]) * W + eox[qd];
                long ob1 = ob + (long)W * W;
                if (OUTM == 0) {
                    out[ob] = v0; out[ob1] = v1;
                } else if (OUTM == 1) {
                    out[ob]  = __uint_as_float(f2tf32(v0));
                    out[ob1] = __uint_as_float(f2tf32(v1));
                } else {
                    unsigned h0 = f2tf32(v0), h1 = f2tf32(v1);
                    out[ob]  = __uint_as_float(h0);
                    out[ob1] = __uint_as_float(h1);
                    outl[ob]  = __uint_as_float(f2tf32(v0 - __uint_as_float(h0)));
                    outl[ob1] = __uint_as_float(f2tf32(v1 - __uint_as_float(h1)));
                }
            }
        }
    }
}

// ------------------- conv1 (scalar, CIN=1), parity-split tf32 output -------------------
template<int CIN, int HIN, int K, int S, int P, int COUT, int CT, int ST>
__global__ void k_conv1(const float* __restrict__ in, const float* __restrict__ w,
                        const float* __restrict__ bias, float* __restrict__ out) {
    constexpr int HOUT = (HIN + 2 * P - K) / S + 1;
    constexpr int KK = K * K;
    __shared__ float sw[CT * CIN * KK];
    const int co0 = blockIdx.y * CT;
    const int n   = blockIdx.z;
    const int t   = threadIdx.x;
    for (int i = t; i < CT * CIN * KK; i += 256) {
        int c = i / (CIN * KK), rest = i % (CIN * KK);
        sw[i] = w[(co0 + c) * CIN * KK + rest];
    }
    __syncthreads();

    const int p0  = (blockIdx.x * 256 + t) * ST;
    const int oy  = p0 / HOUT;
    const int ox0 = p0 % HOUT;

    float acc[CT][ST];
    #pragma unroll
    for (int c = 0; c < CT; c++) {
        float bv = bias[co0 + c];
        #pragma unroll
        for (int s = 0; s < ST; s++) acc[c][s] = bv;
    }

    const float* ib = in + (long)n * CIN * HIN * HIN;
    for (int ci = 0; ci < CIN; ci++) {
        const float* ic = ib + ci * HIN * HIN;
        #pragma unroll
        for (int ky = 0; ky < K; ky++) {
            int iy = oy * S - P + ky;
            if ((unsigned)iy < (unsigned)HIN) {
                const float* row = ic + iy * HIN;
                #pragma unroll
                for (int kx = 0; kx < K; kx++) {
                    float xv[ST];
                    #pragma unroll
                    for (int s = 0; s < ST; s++) {
                        int ix = (ox0 + s) * S - P + kx;
                        xv[s] = ((unsigned)ix < (unsigned)HIN) ? row[ix] : 0.f;
                    }
                    #pragma unroll
                    for (int c = 0; c < CT; c++) {
                        float wv = sw[(c * CIN + ci) * KK + ky * K + kx];
                        #pragma unroll
                        for (int s = 0; s < ST; s++)
                            acc[c][s] = fmaf(xv[s], wv, acc[c][s]);
                    }
                }
            }
        }
    }

    const int py = oy & 1, u = oy >> 1;
    #pragma unroll
    for (int c = 0; c < CT; c++) {
        #pragma unroll
        for (int s = 0; s < ST; s++) {
            int ox = ox0 + s;
            int plane = py * 2 + (ox & 1);
            long ob = ((((long)n * COUT + co0 + c) * 4 + plane) * 32 + u) * 32 + (ox >> 1);
            float v = fmaxf(acc[c][s], 0.f);
            out[ob] = __uint_as_float(f2tf32(v));
        }
    }
}

// ------------------- deconv2: [256,32,64,64] -> [256,1,128,128], sigmoid -------------------
__global__ void k_deconv2(const float* __restrict__ in, const float* __restrict__ w,
                          const float* __restrict__ bias, float* __restrict__ out) {
    __shared__ float sw[512];
    const int t = threadIdx.x;
    const int n = blockIdx.z;
    for (int i = t; i < 512; i += 256) sw[i] = w[i];
    __syncthreads();

    const int ti = blockIdx.x * 256 + t;
    const int ty = ti >> 4, tx = ti & 15;
    const float bv = __ldg(bias);

    float acc[4][8];
    #pragma unroll
    for (int r = 0; r < 4; r++)
        #pragma unroll
        for (int c = 0; c < 8; c++) acc[r][c] = 0.f;

    const float* ib = in + (long)n * 32 * 4096;
    for (int ci = 0; ci < 32; ci++) {
        const float* ic = ib + ci * 4096;
        float xv[4][6];
        #pragma unroll
        for (int rr = 0; rr < 4; rr++) {
            int iy = 2 * ty - 1 + rr;
            bool vy = (unsigned)iy < 64u;
            const float* row = ic + iy * 64;
            int c0 = 4 * tx - 1;
            xv[rr][0] = (vy && c0 >= 0) ? row[c0] : 0.f;
            if (vy) {
                float4 m4 = *(const float4*)(row + 4 * tx);
                xv[rr][1] = m4.x; xv[rr][2] = m4.y; xv[rr][3] = m4.z; xv[rr][4] = m4.w;
            } else {
                xv[rr][1] = xv[rr][2] = xv[rr][3] = xv[rr][4] = 0.f;
            }
            int c5 = 4 * tx + 4;
            xv[rr][5] = (vy && c5 < 64) ? row[c5] : 0.f;
        }
        float wr[16];
        #pragma unroll
        for (int k = 0; k < 16; k++) wr[k] = sw[ci * 16 + k];
        #pragma unroll
        for (int r = 0; r < 4; r++) {
            const int pyy = r & 1;
            const int rowA = (r >> 1) + pyy + 1, rowB = rowA - 1;
            #pragma unroll
            for (int c = 0; c < 8; c++) {
                const int pxx = c & 1;
                const int colA = (c >> 1) + pxx + 1, colB = colA - 1;
                float a = acc[r][c];
                a = fmaf(xv[rowA][colA], wr[(1 - pyy) * 4 + (1 - pxx)], a);
                a = fmaf(xv[rowA][colB], wr[(1 - pyy) * 4 + (3 - pxx)], a);
                a = fmaf(xv[rowB][colA], wr[(3 - pyy) * 4 + (1 - pxx)], a);
                a = fmaf(xv[rowB][colB], wr[(3 - pyy) * 4 + (3 - pxx)], a);
                acc[r][c] = a;
            }
        }
    }

    float* ob = out + (long)n * 16384;
    #pragma unroll
    for (int r = 0; r < 4; r++) {
        int oy = 4 * ty + r;
        float v[8];
        #pragma unroll
        for (int c = 0; c < 8; c++)
            v[c] = 1.f / (1.f + expf(-(acc[r][c] + bv)));
        *(float4*)(ob + oy * 128 + 8 * tx)     = make_float4(v[0], v[1], v[2], v[3]);
        *(float4*)(ob + oy * 128 + 8 * tx + 4) = make_float4(v[4], v[5], v[6], v[7]);
    }
}

// ------------------- VQ on tensor cores (3xTF32, hi/lo z from conv4) -------------------
__global__ void k_vq_tc(const float* __restrict__ zh, const float* __restrict__ zl,
                        const float* __restrict__ cb, const float* __restrict__ cbh,
                        const float* __restrict__ cbl, const float* __restrict__ cn,
                        float* __restrict__ q, float* __restrict__ lpart) {
    __shared__ unsigned As[2][32][136];
    __shared__ unsigned Bs[2][32][40];
    __shared__ float scn[32];
    __shared__ int sidx[128];
    __shared__ float red[256];
    const int t = threadIdx.x, lane = t & 31, wrp = t >> 5;
    const int g = lane >> 2, tg = lane & 3;
    const int n  = blockIdx.x >> 3;
    const int p0 = (blockIdx.x & 7) * 128;
    const int mw = wrp * 16;

    for (int i = t; i < 4096; i += 256) {
        int d = i >> 7, m = i & 127;
        long zi = ((long)n * 32 + d) * 1024 + p0 + m;
        As[0][d][m] = __float_as_uint(zh[zi]);
        As[1][d][m] = __float_as_uint(zl[zi]);
    }
    __syncthreads();

    unsigned ah[4][4], al[4][4];
    #pragma unroll
    for (int s = 0; s < 4; s++) {
        ah[s][0] = As[0][s * 8 + tg][mw + g];     ah[s][1] = As[0][s * 8 + tg][mw + g + 8];
        ah[s][2] = As[0][s * 8 + tg + 4][mw + g]; ah[s][3] = As[0][s * 8 + tg + 4][mw + g + 8];
        al[s][0] = As[1][s * 8 + tg][mw + g];     al[s][1] = As[1][s * 8 + tg][mw + g + 8];
        al[s][2] = As[1][s * 8 + tg + 4][mw + g]; al[s][3] = As[1][s * 8 + tg + 4][mw + g + 8];
    }

    float best0 = 3.4e38f, best1 = 3.4e38f;
    int bidx0 = 0, bidx1 = 0;

    for (int ch = 0; ch < 16; ch++) {
        const int k0 = ch * 32;
        __syncthreads();
        for (int i = t; i < 1024; i += 256) {
            int d = i & 31, kk = i >> 5;
            Bs[0][d][kk] = __float_as_uint(cbh[(k0 + kk) * 32 + d]);
            Bs[1][d][kk] = __float_as_uint(cbl[(k0 + kk) * 32 + d]);
        }
        if (t < 32) scn[t] = cn[k0 + t];
        __syncthreads();

        #pragma unroll
        for (int nt = 0; nt < 4; nt++) {
            float a0 = 0.f, a1 = 0.f, a2 = 0.f, a3 = 0.f;
            #pragma unroll
            for (int s = 0; s < 4; s++) {
                unsigned bh0 = Bs[0][s * 8 + tg][nt * 8 + g], bh1 = Bs[0][s * 8 + tg + 4][nt * 8 + g];
                unsigned bl0 = Bs[1][s * 8 + tg][nt * 8 + g], bl1 = Bs[1][s * 8 + tg + 4][nt * 8 + g];
                mma_tf32(a0, a1, a2, a3, al[s][0], al[s][1], al[s][2], al[s][3], bh0, bh1);
                mma_tf32(a0, a1, a2, a3, ah[s][0], ah[s][1], ah[s][2], ah[s][3], bl0, bl1);
                mma_tf32(a0, a1, a2, a3, ah[s][0], ah[s][1], ah[s][2], ah[s][3], bh0, bh1);
            }
            int kc0 = k0 + nt * 8 + 2 * tg, kc1 = kc0 + 1;
            float c0 = scn[nt * 8 + 2 * tg], c1 = scn[nt * 8 + 2 * tg + 1];
            float d00 = fmaf(-2.f, a0, c0), d01 = fmaf(-2.f, a1, c1);
            float d10 = fmaf(-2.f, a2, c0), d11 = fmaf(-2.f, a3, c1);
            if (d00 < best0) { best0 = d00; bidx0 = kc0; }
            if (d01 < best0) { best0 = d01; bidx0 = kc1; }
            if (d10 < best1) { best1 = d10; bidx1 = kc0; }
            if (d11 < best1) { best1 = d11; bidx1 = kc1; }
        }
    }

    #pragma unroll
    for (int off = 1; off < 4; off <<= 1) {
        float ob; int oi;
        ob = __shfl_down_sync(0xffffffffu, best0, off, 4);
        oi = __shfl_down_sync(0xffffffffu, bidx0, off, 4);
        if (ob < best0 || (ob == best0 && oi < bidx0)) { best0 = ob; bidx0 = oi; }
        ob = __shfl_down_sync(0xffffffffu, best1, off, 4);
        oi = __shfl_down_sync(0xffffffffu, bidx1, off, 4);
        if (ob < best1 || (ob == best1 && oi < bidx1)) { best1 = ob; bidx1 = oi; }
    }
    if (tg == 0) { sidx[mw + g] = bidx0; sidx[mw + g + 8] = bidx1; }
    __syncthreads();

    float lsum = 0.f;
    for (int i = t; i < 4096; i += 256) {
        int d = i >> 7, m = i & 127;
        long zi = ((long)n * 32 + d) * 1024 + p0 + m;
        float qv = __ldg(cb + sidx[m] * 32 + d);
        float zv = zh[zi] + zl[zi];
        q[zi] = __uint_as_float(f2tf32(qv));
        float e = qv - zv;
        lsum = fmaf(e, e, lsum);
    }
    red[t] = lsum;
    __syncthreads();
    for (int s = 128; s > 0; s >>= 1) {
        if (t < s) red[t] += red[t + s];
        __syncthreads();
    }
    if (t == 0) lpart[blockIdx.x] = red[0];
}

// deterministic fixed-order final reduction: vq_loss = 1.26 * mean
__global__ void k_loss(const float* __restrict__ lpart, float* __restrict__ out,
                       int out_size) {
    __shared__ float red[256];
    const int t = threadIdx.x;
    float s = 0.f;
    #pragma unroll
    for (int j = 0; j < 8; j++) s += lpart[t + 256 * j];
    red[t] = s;
    __syncthreads();
    for (int st = 128; st > 0; st >>= 1) {
        if (t < st) red[t] += red[t + st];
        __syncthreads();
    }
    if (t == 0) out[out_size - 1] = 1.26f * red[0] / 8388608.0f;
}

// ------------------- launch -------------------
extern "C" void kernel_launch(void* const* d_in, const int* in_sizes, int n_in,
                              void* d_out, int out_size) {
    const float* x   = (const float*)d_in[0];
    const float* ew1 = (const float*)d_in[1];  const float* eb1 = (const float*)d_in[2];
    const float* ew2 = (const float*)d_in[3];  const float* eb2 = (const float*)d_in[4];
    const float* ew3 = (const float*)d_in[5];  const float* eb3 = (const float*)d_in[6];
    const float* ew4 = (const float*)d_in[7];  const float* eb4 = (const float*)d_in[8];
    const float* cb  = (const float*)d_in[9];
    const float* dw1 = (const float*)d_in[10]; const float* db1 = (const float*)d_in[11];
    const float* tw1 = (const float*)d_in[12]; const float* tb1 = (const float*)d_in[13];
    const float* tw2 = (const float*)d_in[14]; const float* tb2 = (const float*)d_in[15];
    float* out = (float*)d_out;

    float *pa, *pb, *pc, *pz, *pzl, *pq, *pl;
    float *pwb, *pwbl, *pcbh, *pcbl, *pcn;
    cudaGetSymbolAddress((void**)&pa,  g_a);
    cudaGetSymbolAddress((void**)&pb,  g_b);
    cudaGetSymbolAddress((void**)&pc,  g_c);
    cudaGetSymbolAddress((void**)&pz,  g_z);   cudaGetSymbolAddress((void**)&pzl, g_zl);
    cudaGetSymbolAddress((void**)&pq,  g_q);
    cudaGetSymbolAddress((void**)&pl,  g_lpart);
    cudaGetSymbolAddress((void**)&pwb, g_wb);  cudaGetSymbolAddress((void**)&pwbl, g_wbl);
    cudaGetSymbolAddress((void**)&pcbh, g_cbh); cudaGetSymbolAddress((void**)&pcbl, g_cbl);
    cudaGetSymbolAddress((void**)&pcn, g_cn);

    // encoder single-pass tf32 (X3=false); conv4 emits hi/lo of its accumulator for VQ
    auto kc2 = k_igemm<32, 32, 64, 1, 2, 0, 4, false, true,  1, 32, false, true,  1>;
    auto kc3 = k_igemm<64, 32, 64, 1, 3, 1, 9, false, false, 1, 32, false, true,  1>;
    auto kc4 = k_igemm<64, 32, 32, 1, 1, 0, 1, false, false, 1, 32, false, false, 2>;
    auto kd1 = k_igemm<32, 32, 64, 1, 3, 1, 9, false, false, 1, 32, false, true,  1>;
    auto kt1 = k_igemm<64, 32, 32, 1, 1, 0, 4, true,  false, 2, 64, false, true,  0>;
    const int SM_C2 = 20736, SM_C3 = 32256, SM_C4 = 9728, SM_D1 = 32256, SM_T1 = 16640;
    cudaFuncSetAttribute(kc2, cudaFuncAttributeMaxDynamicSharedMemorySize, SM_C2);
    cudaFuncSetAttribute(kc3, cudaFuncAttributeMaxDynamicSharedMemorySize, SM_C3);
    cudaFuncSetAttribute(kc4, cudaFuncAttributeMaxDynamicSharedMemorySize, SM_C4);
    cudaFuncSetAttribute(kd1, cudaFuncAttributeMaxDynamicSharedMemorySize, SM_D1);
    cudaFuncSetAttribute(kt1, cudaFuncAttributeMaxDynamicSharedMemorySize, SM_T1);

    k_prep_all<<<546, 256>>>(ew2, ew3, ew4, dw1, tw1, cb, pwb, pwbl, pcbh, pcbl, pcn);

    // Encoder (conv1 writes parity-split tf32 planes for conv2)
    k_conv1<1, 128, 4, 2, 1, 32, 8, 4><<<dim3(4, 4, BATCH), 256>>>(x, ew1, eb1, pa);
    kc2<<<dim3(4, 1, BATCH), 256, SM_C2>>>(pa, pa, pwb + OFF_C2, pwbl + OFF_C2, eb2, pb, pb);
    kc3<<<dim3(4, 1, BATCH), 256, SM_C3>>>(pb, pb, pwb + OFF_C3, pwbl + OFF_C3, eb3, pc, pc);
    kc4<<<dim3(4, 1, BATCH), 256, SM_C4>>>(pc, pc, pwb + OFF_C4, pwbl + OFF_C4, eb4, pz, pzl);

    // VQ (3xTF32 distances on conv4's hi/lo accumulator)
    k_vq_tc<<<2048, 256>>>(pz, pzl, cb, pcbh, pcbl, pcn, pq, pl);

    // Decoder
    kd1<<<dim3(4, 1, BATCH), 256, SM_D1>>>(pq, pq, pwb + OFF_D1, pwbl + OFF_D1, db1, pc, pc);
    kt1<<<dim3(4, 4, BATCH), 256, SM_T1>>>(pc, pc, pwb + OFF_T1, pwbl + OFF_T1, tb1, pa, pa);
    k_deconv2<<<dim3(2, 1, BATCH), 256>>>(pa, tw2, tb2, out);

    k_loss<<<1, 256>>>(pl, out, out_size);
}

// round 13
// speedup vs baseline: 1.5117x; 1.0678x over previous
#include <cuda_runtime.h>
#include <math.h>

#define BATCH 256

// ------------------- scratch (alloc-free rule: device globals) -------------------
__device__ float g_a [BATCH * 32 * 64 * 64];  // conv1 out (parity-split, tf32) / deconv1 out
__device__ float g_b [BATCH * 64 * 32 * 32];  // conv2 out (tf32)
__device__ float g_c [BATCH * 64 * 32 * 32];  // conv3 out (tf32) / dec1 out (tf32)
__device__ float g_z [BATCH * 32 * 32 * 32];  // z hi
__device__ float g_zl[BATCH * 32 * 32 * 32];  // z lo
__device__ float g_q [BATCH * 32 * 32 * 32];  // quantized latent (tf32-rounded)
__device__ float g_lpart[2048];               // per-block loss partials
__device__ float g_wb [131072];               // prepped weights hi, group-major
__device__ float g_wbl[131072];               // weights lo (legacy; staged only if X3)
__device__ float g_cbh[16384];                // codebook hi (tf32)
__device__ float g_cbl[16384];                // codebook lo (unused by VQ now)
__device__ float g_cn[512];                   // codebook norms (fp32)

// group-major layout: [grp][tap][cig(8)][co]   (conv2: [grp][plane][tap][cig][co])
#define OFF_C2  0
#define OFF_C3  32768
#define OFF_C4  69632
#define OFF_D1  71680
#define OFF_T1  90112

// ------------------- tf32 helpers -------------------
__device__ __forceinline__ unsigned f2tf32(float x) {
    unsigned r;
    asm("cvt.rna.tf32.f32 %0, %1;" : "=r"(r) : "f"(x));
    return r;
}

__device__ __forceinline__ void mma_tf32(float& c0, float& c1, float& c2, float& c3,
                                         unsigned a0, unsigned a1, unsigned a2, unsigned a3,
                                         unsigned b0, unsigned b1) {
    asm volatile("mma.sync.aligned.m16n8k8.row.col.f32.tf32.tf32.f32 "
                 "{%0,%1,%2,%3}, {%4,%5,%6,%7}, {%8,%9}, {%0,%1,%2,%3};"
                 : "+f"(c0), "+f"(c1), "+f"(c2), "+f"(c3)
                 : "r"(a0), "r"(a1), "r"(a2), "r"(a3), "r"(b0), "r"(b1));
}

__host__ __device__ constexpr int calc_pw(int h, int w) {
    int p = w;
    while (((h * p) & 31) != 8) p++;
    return p;
}

// ------------------- fused prep: weights hi/lo (group-major), codebook, norms -------------------
__global__ void k_prep_all(const float* __restrict__ ew2, const float* __restrict__ ew3,
                           const float* __restrict__ ew4, const float* __restrict__ dw1,
                           const float* __restrict__ tw1, const float* __restrict__ cb,
                           float* __restrict__ wbh, float* __restrict__ wbl,
                           float* __restrict__ cbh, float* __restrict__ cbl,
                           float* __restrict__ cn) {
    const int b = blockIdx.x, t = threadIdx.x;
    float v; int oidx;
    if (b < 128) {                       // conv2 parity-split: [grp4][plane4][tap4][cig8][co64]
        int i = b * 256 + t;
        int co = i & 63, r = i >> 6, cig = r & 7, r2 = r >> 3;
        int tap = r2 & 3, r3 = r2 >> 2, plane = r3 & 3, grp = r3 >> 2;
        int py = plane >> 1, px = plane & 1;
        int ty = tap >> 1, tx = tap & 1;
        int ky = (py == 0) ? (ty ? 3 : 1) : (ty ? 2 : 0);
        int kx = (px == 0) ? (tx ? 3 : 1) : (tx ? 2 : 0);
        int ci = grp * 8 + cig;
        v = ew2[(co * 32 + ci) * 16 + ky * 4 + kx]; oidx = OFF_C2 + i;
    } else if (b < 272) {                // conv3: [grp8][tap9][cig8][co64]
        int i = (b - 128) * 256 + t;
        int co = i & 63, r = i >> 6, cig = r & 7, r2 = r >> 3, tap = r2 % 9, grp = r2 / 9;
        int ci = grp * 8 + cig;
        v = ew3[(co * 64 + ci) * 9 + tap]; oidx = OFF_C3 + i;
    } else if (b < 280) {                // conv4: [grp8][cig8][co32]
        int i = (b - 272) * 256 + t;
        int co = i & 31, r = i >> 5, cig = r & 7, grp = r >> 3;
        int ci = grp * 8 + cig;
        v = ew4[co * 64 + ci]; oidx = OFF_C4 + i;
    } else if (b < 352) {                // dec1: [grp4][tap9][cig8][co64]
        int i = (b - 280) * 256 + t;
        int co = i & 63, r = i >> 6, cig = r & 7, r2 = r >> 3, tap = r2 % 9, grp = r2 / 9;
        int ci = grp * 8 + cig;
        v = dw1[(co * 32 + ci) * 9 + tap]; oidx = OFF_D1 + i;
    } else if (b < 480) {                // deconv1: [cls4][grp8][tap4][cig8][co32]
        int i = (b - 352) * 256 + t;
        int co = i & 31, r = i >> 5, cig = r & 7, r2 = r >> 3, tap = r2 & 3, r3 = r2 >> 2;
        int grp = r3 & 7, cls = r3 >> 3;
        int py = cls >> 1, px = cls & 1;
        int ty = tap >> 1, tx = tap & 1;
        int ky = ty ? 3 - py : 1 - py;
        int kx = tx ? 3 - px : 1 - px;
        int ci = grp * 8 + cig;
        v = tw1[(ci * 32 + co) * 16 + ky * 4 + kx]; oidx = OFF_T1 + i;
    } else if (b < 544) {                // codebook hi/lo
        int i = (b - 480) * 256 + t;
        float cv = cb[i];
        unsigned hi = f2tf32(cv);
        cbh[i] = __uint_as_float(hi);
        cbl[i] = __uint_as_float(f2tf32(cv - __uint_as_float(hi)));
        return;
    } else {                             // norms
        int k = (b - 544) * 256 + t;
        if (k < 512) {
            float s = 0.f;
            const float* c = cb + k * 32;
            #pragma unroll
            for (int d = 0; d < 32; d++) s = fmaf(c[d], c[d], s);
            cn[k] = s;
        }
        return;
    }
    unsigned hi = f2tf32(v);
    wbh[oidx] = __uint_as_float(hi);
    wbl[oidx] = __uint_as_float(f2tf32(v - __uint_as_float(hi)));
}

// ------------------- tf32 implicit-GEMM with halo-tile smem staging -------------------
// M-tile 256 (8 warps x 2 m16). Per subgroup: stage halo + all-tap B chunk; one
// barrier pair; barrier-free LDS-fed tap loop with B-register rotation prefetch.
// PSPLIT: stride-2 conv as 4 stride-1 2x2 convs on parity planes.
// OUTM: 0 fp32, 1 tf32-rounded, 2 hi/lo dual (for VQ).
template<int CIN, int HIN, int COUT, int S, int K, int P, int NTAPS,
         bool DECONV, bool PSPLIT, int OS, int W, bool X3, bool RELU, int OUTM>
__global__ void __launch_bounds__(256, 2)
k_igemm(const float* __restrict__ in, const float* __restrict__ inl,
        const float* __restrict__ wbh, const float* __restrict__ wbl,
        const float* __restrict__ bias,
        float* __restrict__ out, float* __restrict__ outl) {
    constexpr int G8 = CIN / 8;
    constexpr int NG = PSPLIT ? G8 * 4 : G8;
    constexpr int NT = COUT / 8;
    constexpr int HH = PSPLIT ? 9  : 7 * S + (DECONV ? 2 : K);
    constexpr int HW = PSPLIT ? 33 : 31 * S + (DECONV ? 2 : K);
    constexpr int PW = calc_pw(HH, HW);
    constexpr int CHS = HH * PW;
    constexpr int BP = COUT + 8;
    constexpr int ASZ = 8 * CHS;
    constexpr int BSZ = NTAPS * 8 * BP;
    constexpr int AS = PSPLIT ? 1 : S;

    extern __shared__ float sm[];
    float* Ah = sm;
    float* Al = Ah + ASZ;
    float* Bh = Ah + (X3 ? 2 : 1) * ASZ;
    float* Bl = Bh + BSZ;

    const int t = threadIdx.x, lane = t & 31, wrp = t >> 5;
    const int g = lane >> 2, tg = lane & 3;
    const int n = blockIdx.z;
    const int m0 = blockIdx.x * 256;
    const int r0 = blockIdx.x * 8;

    int cpy = 0, cpx = 0, cls = 0;
    if (DECONV) { cls = blockIdx.y; cpy = cls >> 1; cpx = cls & 1; }

    int aoff[4];
    #pragma unroll
    for (int q = 0; q < 4; q++) {
        int ml = wrp * 32 + (q >> 1) * 16 + g + (q & 1) * 8;
        int oyl = ml >> 5, ox = ml & 31;
        aoff[q] = tg * CHS + (oyl * AS) * PW + ox * AS;
    }
    const int btg = tg * BP, btg4 = (tg + 4) * BP;

    float acc[NT][2][4];
    #pragma unroll
    for (int i = 0; i < NT; i++)
        #pragma unroll
        for (int mt = 0; mt < 2; mt++)
            #pragma unroll
            for (int j = 0; j < 4; j++) acc[i][mt][j] = 0.f;

    for (int sg = 0; sg < NG; sg++) {
        const int grp   = PSPLIT ? (sg >> 2) : sg;
        const int plane = PSPLIT ? (sg & 3) : 0;
        const int DYMIN = PSPLIT ? -(plane >> 1) : (DECONV ? cpy - 1 : -P);
        const int DXMIN = PSPLIT ? -(plane & 1)  : (DECONV ? cpx - 1 : -P);
        const int ci0 = grp * 8;
        __syncthreads();
        // ---- stage A halo ----
        for (int i = t; i < 8 * HH * HW; i += 256) {
            int ch = i / (HH * HW), rem = i % (HH * HW);
            int rr = rem / HW, cc = rem % HW;
            int iy = (PSPLIT ? r0 : r0 * S) + DYMIN + rr;
            int ix = DXMIN + cc;
            bool ok = (unsigned)iy < (unsigned)HIN && (unsigned)ix < (unsigned)HIN;
            long gi;
            if (PSPLIT)
                gi = (((long)n * CIN + ci0 + ch) * 4 + plane) * (HIN * HIN)
                   + (long)iy * HIN + ix;
            else
                gi = ((long)n * CIN + ci0 + ch) * (HIN * HIN) + (long)iy * HIN + ix;
            int si = ch * CHS + rr * PW + cc;
            Ah[si] = ok ? __ldg(in + gi) : 0.f;
            if (X3) Al[si] = ok ? __ldg(inl + gi) : 0.f;
        }
        // ---- stage B ----
        {
            const long wo = (DECONV ? (long)cls * NG * NTAPS * 8 * COUT : 0)
                          + (long)sg * NTAPS * 8 * COUT;
            for (int i = t; i < NTAPS * 8 * COUT; i += 256) {
                int tap = i / (8 * COUT), rem = i % (8 * COUT);
                int k = rem / COUT, co = rem % COUT;
                int si = tap * 8 * BP + k * BP + co;
                Bh[si] = wbh[wo + i];
                if (X3) Bl[si] = wbl[wo + i];
            }
        }
        __syncthreads();

        // ---- barrier-free tap loop (B rotation prefetch) ----
        for (int tap = 0; tap < NTAPS; tap++) {
            int ty, tx;
            if (PSPLIT)      { ty = tap >> 1;                          tx = tap & 1; }
            else if (DECONV) { ty = (cpy - (tap >> 1)) - DYMIN;        tx = (cpx - (tap & 1)) - DXMIN; }
            else             { ty = tap / K;                           tx = tap % K; }
            const int toff = ty * PW + tx;

            unsigned ah[2][4], al[2][4];
            #pragma unroll
            for (int q = 0; q < 4; q++) {
                int si = aoff[q] + toff;
                int mt = q >> 1, h = q & 1;
                ah[mt][h]     = __float_as_uint(Ah[si]);
                ah[mt][2 + h] = __float_as_uint(Ah[si + 4 * CHS]);
                if (X3) {
                    al[mt][h]     = __float_as_uint(Al[si]);
                    al[mt][2 + h] = __float_as_uint(Al[si + 4 * CHS]);
                }
            }

            const float* Bth = Bh + tap * 8 * BP;
            const float* Btl = Bl + tap * 8 * BP;
            // preload nt=0 B regs, rotate ahead of MMAs
            unsigned pbh0 = __float_as_uint(Bth[btg + g]);
            unsigned pbh1 = __float_as_uint(Bth[btg4 + g]);
            unsigned pbl0 = 0, pbl1 = 0;
            if (X3) {
                pbl0 = __float_as_uint(Btl[btg + g]);
                pbl1 = __float_as_uint(Btl[btg4 + g]);
            }
            #pragma unroll
            for (int nt = 0; nt < NT; nt++) {
                unsigned bh0 = pbh0, bh1 = pbh1, bl0 = pbl0, bl1 = pbl1;
                if (nt + 1 < NT) {
                    pbh0 = __float_as_uint(Bth[btg + (nt + 1) * 8 + g]);
                    pbh1 = __float_as_uint(Bth[btg4 + (nt + 1) * 8 + g]);
                    if (X3) {
                        pbl0 = __float_as_uint(Btl[btg + (nt + 1) * 8 + g]);
                        pbl1 = __float_as_uint(Btl[btg4 + (nt + 1) * 8 + g]);
                    }
                }
                #pragma unroll
                for (int mt = 0; mt < 2; mt++) {
                    if (X3) {
                        mma_tf32(acc[nt][mt][0], acc[nt][mt][1], acc[nt][mt][2], acc[nt][mt][3],
                                 al[mt][0], al[mt][1], al[mt][2], al[mt][3], bh0, bh1);
                        mma_tf32(acc[nt][mt][0], acc[nt][mt][1], acc[nt][mt][2], acc[nt][mt][3],
                                 ah[mt][0], ah[mt][1], ah[mt][2], ah[mt][3], bl0, bl1);
                    }
                    mma_tf32(acc[nt][mt][0], acc[nt][mt][1], acc[nt][mt][2], acc[nt][mt][3],
                             ah[mt][0], ah[mt][1], ah[mt][2], ah[mt][3], bh0, bh1);
                }
            }
        }
    }

    // ---- epilogue: direct strided stores ----
    int eoy[4], eox[4];
    #pragma unroll
    for (int q = 0; q < 4; q++) {
        int m = m0 + wrp * 32 + (q >> 1) * 16 + ((q & 1) ? g + 8 : g);
        eoy[q] = (m >> 5) * OS + cpy;
        eox[q] = (m & 31) * OS + cpx;
    }
    #pragma unroll
    for (int nt = 0; nt < NT; nt++) {
        int co = nt * 8 + 2 * tg;
        float b0 = __ldg(bias + co), b1 = __ldg(bias + co + 1);
        #pragma unroll
        for (int mt = 0; mt < 2; mt++) {
            #pragma unroll
            for (int hh = 0; hh < 2; hh++) {
                int qd = mt * 2 + hh;
                float v0 = acc[nt][mt][hh * 2 + 0] + b0;
                float v1 = acc[nt][mt][hh * 2 + 1] + b1;
                if (RELU) { v0 = fmaxf(v0, 0.f); v1 = fmaxf(v1, 0.f); }
                long ob = (((long)n * COUT + co) * W + eoy[qd]) * W + eox[qd];
                long ob1 = ob + (long)W * W;
                if (OUTM == 0) {
                    out[ob] = v0; out[ob1] = v1;
                } else if (OUTM == 1) {
                    out[ob]  = __uint_as_float(f2tf32(v0));
                    out[ob1] = __uint_as_float(f2tf32(v1));
                } else {
                    unsigned h0 = f2tf32(v0), h1 = f2tf32(v1);
                    out[ob]  = __uint_as_float(h0);
                    out[ob1] = __uint_as_float(h1);
                    outl[ob]  = __uint_as_float(f2tf32(v0 - __uint_as_float(h0)));
                    outl[ob1] = __uint_as_float(f2tf32(v1 - __uint_as_float(h1)));
                }
            }
        }
    }
}

// ------------------- conv1 (scalar, CIN=1), parity-split tf32 output -------------------
template<int CIN, int HIN, int K, int S, int P, int COUT, int CT, int ST>
__global__ void k_conv1(const float* __restrict__ in, const float* __restrict__ w,
                        const float* __restrict__ bias, float* __restrict__ out) {
    constexpr int HOUT = (HIN + 2 * P - K) / S + 1;
    constexpr int KK = K * K;
    __shared__ float sw[CT * CIN * KK];
    const int co0 = blockIdx.y * CT;
    const int n   = blockIdx.z;
    const int t   = threadIdx.x;
    for (int i = t; i < CT * CIN * KK; i += 256) {
        int c = i / (CIN * KK), rest = i % (CIN * KK);
        sw[i] = w[(co0 + c) * CIN * KK + rest];
    }
    __syncthreads();

    const int p0  = (blockIdx.x * 256 + t) * ST;
    const int oy  = p0 / HOUT;
    const int ox0 = p0 % HOUT;

    float acc[CT][ST];
    #pragma unroll
    for (int c = 0; c < CT; c++) {
        float bv = bias[co0 + c];
        #pragma unroll
        for (int s = 0; s < ST; s++) acc[c][s] = bv;
    }

    const float* ib = in + (long)n * CIN * HIN * HIN;
    for (int ci = 0; ci < CIN; ci++) {
        const float* ic = ib + ci * HIN * HIN;
        #pragma unroll
        for (int ky = 0; ky < K; ky++) {
            int iy = oy * S - P + ky;
            if ((unsigned)iy < (unsigned)HIN) {
                const float* row = ic + iy * HIN;
                #pragma unroll
                for (int kx = 0; kx < K; kx++) {
                    float xv[ST];
                    #pragma unroll
                    for (int s = 0; s < ST; s++) {
                        int ix = (ox0 + s) * S - P + kx;
                        xv[s] = ((unsigned)ix < (unsigned)HIN) ? row[ix] : 0.f;
                    }
                    #pragma unroll
                    for (int c = 0; c < CT; c++) {
                        float wv = sw[(c * CIN + ci) * KK + ky * K + kx];
                        #pragma unroll
                        for (int s = 0; s < ST; s++)
                            acc[c][s] = fmaf(xv[s], wv, acc[c][s]);
                    }
                }
            }
        }
    }

    const int py = oy & 1, u = oy >> 1;
    #pragma unroll
    for (int c = 0; c < CT; c++) {
        #pragma unroll
        for (int s = 0; s < ST; s++) {
            int ox = ox0 + s;
            int plane = py * 2 + (ox & 1);
            long ob = ((((long)n * COUT + co0 + c) * 4 + plane) * 32 + u) * 32 + (ox >> 1);
            float v = fmaxf(acc[c][s], 0.f);
            out[ob] = __uint_as_float(f2tf32(v));
        }
    }
}

// ------------------- deconv2: [256,32,64,64] -> [256,1,128,128], sigmoid -------------------
__global__ void k_deconv2(const float* __restrict__ in, const float* __restrict__ w,
                          const float* __restrict__ bias, float* __restrict__ out) {
    __shared__ float sw[512];
    const int t = threadIdx.x;
    const int n = blockIdx.z;
    for (int i = t; i < 512; i += 256) sw[i] = w[i];
    __syncthreads();

    const int ti = blockIdx.x * 256 + t;
    const int ty = ti >> 4, tx = ti & 15;
    const float bv = __ldg(bias);

    float acc[4][8];
    #pragma unroll
    for (int r = 0; r < 4; r++)
        #pragma unroll
        for (int c = 0; c < 8; c++) acc[r][c] = 0.f;

    const float* ib = in + (long)n * 32 * 4096;
    for (int ci = 0; ci < 32; ci++) {
        const float* ic = ib + ci * 4096;
        float xv[4][6];
        #pragma unroll
        for (int rr = 0; rr < 4; rr++) {
            int iy = 2 * ty - 1 + rr;
            bool vy = (unsigned)iy < 64u;
            const float* row = ic + iy * 64;
            int c0 = 4 * tx - 1;
            xv[rr][0] = (vy && c0 >= 0) ? row[c0] : 0.f;
            if (vy) {
                float4 m4 = *(const float4*)(row + 4 * tx);
                xv[rr][1] = m4.x; xv[rr][2] = m4.y; xv[rr][3] = m4.z; xv[rr][4] = m4.w;
            } else {
                xv[rr][1] = xv[rr][2] = xv[rr][3] = xv[rr][4] = 0.f;
            }
            int c5 = 4 * tx + 4;
            xv[rr][5] = (vy && c5 < 64) ? row[c5] : 0.f;
        }
        float wr[16];
        #pragma unroll
        for (int k = 0; k < 16; k++) wr[k] = sw[ci * 16 + k];
        #pragma unroll
        for (int r = 0; r < 4; r++) {
            const int pyy = r & 1;
            const int rowA = (r >> 1) + pyy + 1, rowB = rowA - 1;
            #pragma unroll
            for (int c = 0; c < 8; c++) {
                const int pxx = c & 1;
                const int colA = (c >> 1) + pxx + 1, colB = colA - 1;
                float a = acc[r][c];
                a = fmaf(xv[rowA][colA], wr[(1 - pyy) * 4 + (1 - pxx)], a);
                a = fmaf(xv[rowA][colB], wr[(1 - pyy) * 4 + (3 - pxx)], a);
                a = fmaf(xv[rowB][colA], wr[(3 - pyy) * 4 + (1 - pxx)], a);
                a = fmaf(xv[rowB][colB], wr[(3 - pyy) * 4 + (3 - pxx)], a);
                acc[r][c] = a;
            }
        }
    }

    float* ob = out + (long)n * 16384;
    #pragma unroll
    for (int r = 0; r < 4; r++) {
        int oy = 4 * ty + r;
        float v[8];
        #pragma unroll
        for (int c = 0; c < 8; c++)
            v[c] = 1.f / (1.f + expf(-(acc[r][c] + bv)));
        *(float4*)(ob + oy * 128 + 8 * tx)     = make_float4(v[0], v[1], v[2], v[3]);
        *(float4*)(ob + oy * 128 + 8 * tx + 4) = make_float4(v[4], v[5], v[6], v[7]);
    }
}

// ------------------- VQ on tensor cores (1xTF32 distances; exact-z loss) -------------------
__global__ void k_vq_tc(const float* __restrict__ zh, const float* __restrict__ zl,
                        const float* __restrict__ cb, const float* __restrict__ cbh,
                        const float* __restrict__ cn,
                        float* __restrict__ q, float* __restrict__ lpart) {
    __shared__ unsigned As[32][136];
    __shared__ unsigned Bs[32][40];
    __shared__ float scn[32];
    __shared__ int sidx[128];
    __shared__ float red[256];
    const int t = threadIdx.x, lane = t & 31, wrp = t >> 5;
    const int g = lane >> 2, tg = lane & 3;
    const int n  = blockIdx.x >> 3;
    const int p0 = (blockIdx.x & 7) * 128;
    const int mw = wrp * 16;

    for (int i = t; i < 4096; i += 256) {
        int d = i >> 7, m = i & 127;
        long zi = ((long)n * 32 + d) * 1024 + p0 + m;
        As[d][m] = __float_as_uint(zh[zi]);
    }
    __syncthreads();

    unsigned ah[4][4];
    #pragma unroll
    for (int s = 0; s < 4; s++) {
        ah[s][0] = As[s * 8 + tg][mw + g];     ah[s][1] = As[s * 8 + tg][mw + g + 8];
        ah[s][2] = As[s * 8 + tg + 4][mw + g]; ah[s][3] = As[s * 8 + tg + 4][mw + g + 8];
    }

    float best0 = 3.4e38f, best1 = 3.4e38f;
    int bidx0 = 0, bidx1 = 0;

    for (int ch = 0; ch < 16; ch++) {
        const int k0 = ch * 32;
        __syncthreads();
        for (int i = t; i < 1024; i += 256) {
            int d = i & 31, kk = i >> 5;
            Bs[d][kk] = __float_as_uint(cbh[(k0 + kk) * 32 + d]);
        }
        if (t < 32) scn[t] = cn[k0 + t];
        __syncthreads();

        #pragma unroll
        for (int nt = 0; nt < 4; nt++) {
            float a0 = 0.f, a1 = 0.f, a2 = 0.f, a3 = 0.f;
            #pragma unroll
            for (int s = 0; s < 4; s++) {
                unsigned bh0 = Bs[s * 8 + tg][nt * 8 + g];
                unsigned bh1 = Bs[s * 8 + tg + 4][nt * 8 + g];
                mma_tf32(a0, a1, a2, a3, ah[s][0], ah[s][1], ah[s][2], ah[s][3], bh0, bh1);
            }
            int kc0 = k0 + nt * 8 + 2 * tg, kc1 = kc0 + 1;
            float c0 = scn[nt * 8 + 2 * tg], c1 = scn[nt * 8 + 2 * tg + 1];
            float d00 = fmaf(-2.f, a0, c0), d01 = fmaf(-2.f, a1, c1);
            float d10 = fmaf(-2.f, a2, c0), d11 = fmaf(-2.f, a3, c1);
            if (d00 < best0) { best0 = d00; bidx0 = kc0; }
            if (d01 < best0) { best0 = d01; bidx0 = kc1; }
            if (d10 < best1) { best1 = d10; bidx1 = kc0; }
            if (d11 < best1) { best1 = d11; bidx1 = kc1; }
        }
    }

    #pragma unroll
    for (int off = 1; off < 4; off <<= 1) {
        float ob; int oi;
        ob = __shfl_down_sync(0xffffffffu, best0, off, 4);
        oi = __shfl_down_sync(0xffffffffu, bidx0, off, 4);
        if (ob < best0 || (ob == best0 && oi < bidx0)) { best0 = ob; bidx0 = oi; }
        ob = __shfl_down_sync(0xffffffffu, best1, off, 4);
        oi = __shfl_down_sync(0xffffffffu, bidx1, off, 4);
        if (ob < best1 || (ob == best1 && oi < bidx1)) { best1 = ob; bidx1 = oi; }
    }
    if (tg == 0) { sidx[mw + g] = bidx0; sidx[mw + g + 8] = bidx1; }
    __syncthreads();

    float lsum = 0.f;
    for (int i = t; i < 4096; i += 256) {
        int d = i >> 7, m = i & 127;
        long zi = ((long)n * 32 + d) * 1024 + p0 + m;
        float qv = __ldg(cb + sidx[m] * 32 + d);
        float zv = zh[zi] + zl[zi];
        q[zi] = __uint_as_float(f2tf32(qv));
        float e = qv - zv;
        lsum = fmaf(e, e, lsum);
    }
    red[t] = lsum;
    __syncthreads();
    for (int s = 128; s > 0; s >>= 1) {
        if (t < s) red[t] += red[t + s];
        __syncthreads();
    }
    if (t == 0) lpart[blockIdx.x] = red[0];
}

// deterministic fixed-order final reduction: vq_loss = 1.26 * mean
__global__ void k_loss(const float* __restrict__ lpart, float* __restrict__ out,
                       int out_size) {
    __shared__ float red[256];
    const int t = threadIdx.x;
    float s = 0.f;
    #pragma unroll
    for (int j = 0; j < 8; j++) s += lpart[t + 256 * j];
    red[t] = s;
    __syncthreads();
    for (int st = 128; st > 0; st >>= 1) {
        if (t < st) red[t] += red[t + st];
        __syncthreads();
    }
    if (t == 0) out[out_size - 1] = 1.26f * red[0] / 8388608.0f;
}

// ------------------- launch -------------------
extern "C" void kernel_launch(void* const* d_in, const int* in_sizes, int n_in,
                              void* d_out, int out_size) {
    const float* x   = (const float*)d_in[0];
    const float* ew1 = (const float*)d_in[1];  const float* eb1 = (const float*)d_in[2];
    const float* ew2 = (const float*)d_in[3];  const float* eb2 = (const float*)d_in[4];
    const float* ew3 = (const float*)d_in[5];  const float* eb3 = (const float*)d_in[6];
    const float* ew4 = (const float*)d_in[7];  const float* eb4 = (const float*)d_in[8];
    const float* cb  = (const float*)d_in[9];
    const float* dw1 = (const float*)d_in[10]; const float* db1 = (const float*)d_in[11];
    const float* tw1 = (const float*)d_in[12]; const float* tb1 = (const float*)d_in[13];
    const float* tw2 = (const float*)d_in[14]; const float* tb2 = (const float*)d_in[15];
    float* out = (float*)d_out;

    float *pa, *pb, *pc, *pz, *pzl, *pq, *pl;
    float *pwb, *pwbl, *pcbh, *pcbl, *pcn;
    cudaGetSymbolAddress((void**)&pa,  g_a);
    cudaGetSymbolAddress((void**)&pb,  g_b);
    cudaGetSymbolAddress((void**)&pc,  g_c);
    cudaGetSymbolAddress((void**)&pz,  g_z);   cudaGetSymbolAddress((void**)&pzl, g_zl);
    cudaGetSymbolAddress((void**)&pq,  g_q);
    cudaGetSymbolAddress((void**)&pl,  g_lpart);
    cudaGetSymbolAddress((void**)&pwb, g_wb);  cudaGetSymbolAddress((void**)&pwbl, g_wbl);
    cudaGetSymbolAddress((void**)&pcbh, g_cbh); cudaGetSymbolAddress((void**)&pcbl, g_cbl);
    cudaGetSymbolAddress((void**)&pcn, g_cn);

    auto kc2 = k_igemm<32, 32, 64, 1, 2, 0, 4, false, true,  1, 32, false, true,  1>;
    auto kc3 = k_igemm<64, 32, 64, 1, 3, 1, 9, false, false, 1, 32, false, true,  1>;
    auto kc4 = k_igemm<64, 32, 32, 1, 1, 0, 1, false, false, 1, 32, false, false, 2>;
    auto kd1 = k_igemm<32, 32, 64, 1, 3, 1, 9, false, false, 1, 32, false, true,  1>;
    auto kt1 = k_igemm<64, 32, 32, 1, 1, 0, 4, true,  false, 2, 64, false, true,  0>;
    const int SM_C2 = 20736, SM_C3 = 32256, SM_C4 = 9728, SM_D1 = 32256, SM_T1 = 16640;
    cudaFuncSetAttribute(kc2, cudaFuncAttributeMaxDynamicSharedMemorySize, SM_C2);
    cudaFuncSetAttribute(kc3, cudaFuncAttributeMaxDynamicSharedMemorySize, SM_C3);
    cudaFuncSetAttribute(kc4, cudaFuncAttributeMaxDynamicSharedMemorySize, SM_C4);
    cudaFuncSetAttribute(kd1, cudaFuncAttributeMaxDynamicSharedMemorySize, SM_D1);
    cudaFuncSetAttribute(kt1, cudaFuncAttributeMaxDynamicSharedMemorySize, SM_T1);

    k_prep_all<<<546, 256>>>(ew2, ew3, ew4, dw1, tw1, cb, pwb, pwbl, pcbh, pcbl, pcn);

    // Encoder (conv1 writes parity-split tf32 planes for conv2)
    k_conv1<1, 128, 4, 2, 1, 32, 8, 4><<<dim3(4, 4, BATCH), 256>>>(x, ew1, eb1, pa);
    kc2<<<dim3(4, 1, BATCH), 256, SM_C2>>>(pa, pa, pwb + OFF_C2, pwbl + OFF_C2, eb2, pb, pb);
    kc3<<<dim3(4, 1, BATCH), 256, SM_C3>>>(pb, pb, pwb + OFF_C3, pwbl + OFF_C3, eb3, pc, pc);
    kc4<<<dim3(4, 1, BATCH), 256, SM_C4>>>(pc, pc, pwb + OFF_C4, pwbl + OFF_C4, eb4, pz, pzl);

    // VQ (1xTF32 distances; loss exact in z via hi+lo)
    k_vq_tc<<<2048, 256>>>(pz, pzl, cb, pcbh, pcn, pq, pl);

    // Decoder
    kd1<<<dim3(4, 1, BATCH), 256, SM_D1>>>(pq, pq, pwb + OFF_D1, pwbl + OFF_D1, db1, pc, pc);
    kt1<<<dim3(4, 4, BATCH), 256, SM_T1>>>(pc, pc, pwb + OFF_T1, pwbl + OFF_T1, tb1, pa, pa);
    k_deconv2<<<dim3(2, 1, BATCH), 256>>>(pa, tw2, tb2, out);

    k_loss<<<1, 256>>>(pl, out, out_size);
}

// round 14
// speedup vs baseline: 2.1059x; 1.3931x over previous
#include <cuda_runtime.h>
#include <math.h>

#define BATCH 256

// ------------------- scratch (alloc-free rule: device globals) -------------------
__device__ float g_a [BATCH * 32 * 64 * 64];  // conv1 out (parity-split, tf32) / deconv1 out
__device__ float g_b [BATCH * 64 * 32 * 32];  // conv2 out (tf32)
__device__ float g_c [BATCH * 64 * 32 * 32];  // conv3 out (tf32) / dec1 out (tf32)
__device__ float g_z [BATCH * 32 * 32 * 32];  // z hi
__device__ float g_zl[BATCH * 32 * 32 * 32];  // z lo
__device__ float g_q [BATCH * 32 * 32 * 32];  // quantized latent (tf32-rounded)
__device__ float g_lpart[2048];               // per-block loss partials
__device__ float g_wb [131072];               // prepped weights (tf32), group-major
__device__ float g_cbh[16384];                // codebook (tf32)
__device__ float g_cn[512];                   // codebook norms (fp32)

// group-major layout: [grp][tap][cig(8)][co]   (conv2: [grp][plane][tap][cig][co])
#define OFF_C2  0
#define OFF_C3  32768
#define OFF_C4  69632
#define OFF_D1  71680
#define OFF_T1  90112

// ------------------- helpers -------------------
__device__ __forceinline__ unsigned f2tf32(float x) {
    unsigned r;
    asm("cvt.rna.tf32.f32 %0, %1;" : "=r"(r) : "f"(x));
    return r;
}

__device__ __forceinline__ void mma_tf32(float& c0, float& c1, float& c2, float& c3,
                                         unsigned a0, unsigned a1, unsigned a2, unsigned a3,
                                         unsigned b0, unsigned b1) {
    asm volatile("mma.sync.aligned.m16n8k8.row.col.f32.tf32.tf32.f32 "
                 "{%0,%1,%2,%3}, {%4,%5,%6,%7}, {%8,%9}, {%0,%1,%2,%3};"
                 : "+f"(c0), "+f"(c1), "+f"(c2), "+f"(c3)
                 : "r"(a0), "r"(a1), "r"(a2), "r"(a3), "r"(b0), "r"(b1));
}

__device__ __forceinline__ void cp_async4(unsigned saddr, const float* gptr, int okbytes) {
    asm volatile("cp.async.ca.shared.global [%0], [%1], 4, %2;"
                 :: "r"(saddr), "l"(gptr), "r"(okbytes));
}
__device__ __forceinline__ void cp_commit() {
    asm volatile("cp.async.commit_group;");
}
template<int N>
__device__ __forceinline__ void cp_wait() {
    asm volatile("cp.async.wait_group %0;" :: "n"(N));
}

__host__ __device__ constexpr int calc_pw(int h, int w) {
    int p = w;
    while (((h * p) & 31) != 8) p++;
    return p;
}

// ------------------- fused prep: weights (group-major tf32), codebook, norms -------------------
__global__ void k_prep_all(const float* __restrict__ ew2, const float* __restrict__ ew3,
                           const float* __restrict__ ew4, const float* __restrict__ dw1,
                           const float* __restrict__ tw1, const float* __restrict__ cb,
                           float* __restrict__ wbh, float* __restrict__ cbh,
                           float* __restrict__ cn) {
    const int b = blockIdx.x, t = threadIdx.x;
    float v; int oidx;
    if (b < 128) {                       // conv2 parity-split: [grp4][plane4][tap4][cig8][co64]
        int i = b * 256 + t;
        int co = i & 63, r = i >> 6, cig = r & 7, r2 = r >> 3;
        int tap = r2 & 3, r3 = r2 >> 2, plane = r3 & 3, grp = r3 >> 2;
        int py = plane >> 1, px = plane & 1;
        int ty = tap >> 1, tx = tap & 1;
        int ky = (py == 0) ? (ty ? 3 : 1) : (ty ? 2 : 0);
        int kx = (px == 0) ? (tx ? 3 : 1) : (tx ? 2 : 0);
        int ci = grp * 8 + cig;
        v = ew2[(co * 32 + ci) * 16 + ky * 4 + kx]; oidx = OFF_C2 + i;
    } else if (b < 272) {                // conv3: [grp8][tap9][cig8][co64]
        int i = (b - 128) * 256 + t;
        int co = i & 63, r = i >> 6, cig = r & 7, r2 = r >> 3, tap = r2 % 9, grp = r2 / 9;
        int ci = grp * 8 + cig;
        v = ew3[(co * 64 + ci) * 9 + tap]; oidx = OFF_C3 + i;
    } else if (b < 280) {                // conv4: [grp8][cig8][co32]
        int i = (b - 272) * 256 + t;
        int co = i & 31, r = i >> 5, cig = r & 7, grp = r >> 3;
        int ci = grp * 8 + cig;
        v = ew4[co * 64 + ci]; oidx = OFF_C4 + i;
    } else if (b < 352) {                // dec1: [grp4][tap9][cig8][co64]
        int i = (b - 280) * 256 + t;
        int co = i & 63, r = i >> 6, cig = r & 7, r2 = r >> 3, tap = r2 % 9, grp = r2 / 9;
        int ci = grp * 8 + cig;
        v = dw1[(co * 32 + ci) * 9 + tap]; oidx = OFF_D1 + i;
    } else if (b < 480) {                // deconv1: [cls4][grp8][tap4][cig8][co32]
        int i = (b - 352) * 256 + t;
        int co = i & 31, r = i >> 5, cig = r & 7, r2 = r >> 3, tap = r2 & 3, r3 = r2 >> 2;
        int grp = r3 & 7, cls = r3 >> 3;
        int py = cls >> 1, px = cls & 1;
        int ty = tap >> 1, tx = tap & 1;
        int ky = ty ? 3 - py : 1 - py;
        int kx = tx ? 3 - px : 1 - px;
        int ci = grp * 8 + cig;
        v = tw1[(ci * 32 + co) * 16 + ky * 4 + kx]; oidx = OFF_T1 + i;
    } else if (b < 544) {                // codebook tf32
        int i = (b - 480) * 256 + t;
        cbh[i] = __uint_as_float(f2tf32(cb[i]));
        return;
    } else {                             // norms
        int k = (b - 544) * 256 + t;
        if (k < 512) {
            float s = 0.f;
            const float* c = cb + k * 32;
            #pragma unroll
            for (int d = 0; d < 32; d++) s = fmaf(c[d], c[d], s);
            cn[k] = s;
        }
        return;
    }
    wbh[oidx] = __uint_as_float(f2tf32(v));
}

// ------------------- tf32 implicit-GEMM, halo staging via cp.async double-buffer -------------------
// M-tile 256 (8 warps x 2 m16). Pipeline: issue stage(g+1) async, wait stage(g),
// compute taps. PSPLIT: stride-2 conv as 4 stride-1 2x2 convs on parity planes.
// OUTM: 0 fp32, 1 tf32-rounded, 2 hi/lo dual (for VQ).
template<int CIN, int HIN, int COUT, int S, int K, int P, int NTAPS,
         bool DECONV, bool PSPLIT, int OS, int W, bool RELU, int OUTM>
__global__ void __launch_bounds__(256, 2)
k_igemm(const float* __restrict__ in, const float* __restrict__ wbh,
        const float* __restrict__ bias,
        float* __restrict__ out, float* __restrict__ outl) {
    constexpr int G8 = CIN / 8;
    constexpr int NG = PSPLIT ? G8 * 4 : G8;
    constexpr int NT = COUT / 8;
    constexpr int HH = PSPLIT ? 9  : 7 * S + (DECONV ? 2 : K);
    constexpr int HW = PSPLIT ? 33 : 31 * S + (DECONV ? 2 : K);
    constexpr int PW = calc_pw(HH, HW);
    constexpr int CHS = HH * PW;
    constexpr int BP = COUT + 8;
    constexpr int ASZ = 8 * CHS;
    constexpr int BSZ = NTAPS * 8 * BP;
    constexpr int BUF = ASZ + BSZ;
    constexpr int AS = PSPLIT ? 1 : S;

    extern __shared__ float sm[];

    const int t = threadIdx.x, lane = t & 31, wrp = t >> 5;
    const int g = lane >> 2, tg = lane & 3;
    const int n = blockIdx.z;
    const int m0 = blockIdx.x * 256;
    const int r0 = blockIdx.x * 8;

    int cpy = 0, cpx = 0, cls = 0;
    if (DECONV) { cls = blockIdx.y; cpy = cls >> 1; cpx = cls & 1; }

    int aoff[4];
    #pragma unroll
    for (int q = 0; q < 4; q++) {
        int ml = wrp * 32 + (q >> 1) * 16 + g + (q & 1) * 8;
        int oyl = ml >> 5, ox = ml & 31;
        aoff[q] = tg * CHS + (oyl * AS) * PW + ox * AS;
    }
    const int btg = tg * BP, btg4 = (tg + 4) * BP;

    float acc[NT][2][4];
    #pragma unroll
    for (int i = 0; i < NT; i++)
        #pragma unroll
        for (int mt = 0; mt < 2; mt++)
            #pragma unroll
            for (int j = 0; j < 4; j++) acc[i][mt][j] = 0.f;

    // async stage of one subgroup into buffer buf
    auto stage = [&](int sg, int buf) {
        const int grp   = PSPLIT ? (sg >> 2) : sg;
        const int plane = PSPLIT ? (sg & 3) : 0;
        const int DYMIN = PSPLIT ? -(plane >> 1) : (DECONV ? cpy - 1 : -P);
        const int DXMIN = PSPLIT ? -(plane & 1)  : (DECONV ? cpx - 1 : -P);
        const int ci0 = grp * 8;
        unsigned abase = (unsigned)__cvta_generic_to_shared(sm + buf * BUF);
        // A halo
        for (int i = t; i < 8 * HH * HW; i += 256) {
            int ch = i / (HH * HW), rem = i % (HH * HW);
            int rr = rem / HW, cc = rem % HW;
            int iy = (PSPLIT ? r0 : r0 * S) + DYMIN + rr;
            int ix = DXMIN + cc;
            bool ok = (unsigned)iy < (unsigned)HIN && (unsigned)ix < (unsigned)HIN;
            long gi;
            if (PSPLIT)
                gi = (((long)n * CIN + ci0 + ch) * 4 + plane) * (HIN * HIN)
                   + (long)iy * HIN + ix;
            else
                gi = ((long)n * CIN + ci0 + ch) * (HIN * HIN) + (long)iy * HIN + ix;
            int si = ch * CHS + rr * PW + cc;
            cp_async4(abase + si * 4, in + gi, ok ? 4 : 0);
        }
        // B (all taps of this subgroup)
        unsigned bbase = abase + ASZ * 4;
        const long wo = (DECONV ? (long)cls * NG * NTAPS * 8 * COUT : 0)
                      + (long)sg * NTAPS * 8 * COUT;
        for (int i = t; i < NTAPS * 8 * COUT; i += 256) {
            int tap = i / (8 * COUT), rem = i % (8 * COUT);
            int k = rem / COUT, co = rem % COUT;
            int si = tap * 8 * BP + k * BP + co;
            cp_async4(bbase + si * 4, wbh + wo + i, 4);
        }
        cp_commit();
    };

    stage(0, 0);
    for (int sg = 0; sg < NG; sg++) {
        const int b = sg & 1;
        if (sg + 1 < NG) { stage(sg + 1, b ^ 1); cp_wait<1>(); }
        else             { cp_wait<0>(); }
        __syncthreads();

        const float* Ab = sm + b * BUF;
        const float* Bb = Ab + ASZ;

        for (int tap = 0; tap < NTAPS; tap++) {
            int ty, tx;
            if (PSPLIT)      { ty = tap >> 1;            tx = tap & 1; }
            else if (DECONV) { ty = 1 - (tap >> 1);      tx = 1 - (tap & 1); }
            else             { ty = tap / K;             tx = tap % K; }
            const int toff = ty * PW + tx;

            unsigned ah[2][4];
            #pragma unroll
            for (int q = 0; q < 4; q++) {
                int si = aoff[q] + toff;
                int mt = q >> 1, h = q & 1;
                ah[mt][h]     = __float_as_uint(Ab[si]);
                ah[mt][2 + h] = __float_as_uint(Ab[si + 4 * CHS]);
            }

            const float* Bth = Bb + tap * 8 * BP;
            unsigned pbh0 = __float_as_uint(Bth[btg + g]);
            unsigned pbh1 = __float_as_uint(Bth[btg4 + g]);
            #pragma unroll
            for (int nt = 0; nt < NT; nt++) {
                unsigned bh0 = pbh0, bh1 = pbh1;
                if (nt + 1 < NT) {
                    pbh0 = __float_as_uint(Bth[btg + (nt + 1) * 8 + g]);
                    pbh1 = __float_as_uint(Bth[btg4 + (nt + 1) * 8 + g]);
                }
                #pragma unroll
                for (int mt = 0; mt < 2; mt++)
                    mma_tf32(acc[nt][mt][0], acc[nt][mt][1], acc[nt][mt][2], acc[nt][mt][3],
                             ah[mt][0], ah[mt][1], ah[mt][2], ah[mt][3], bh0, bh1);
            }
        }
        __syncthreads();
    }

    // ---- epilogue: direct strided stores ----
    int eoy[4], eox[4];
    #pragma unroll
    for (int q = 0; q < 4; q++) {
        int m = m0 + wrp * 32 + (q >> 1) * 16 + ((q & 1) ? g + 8 : g);
        eoy[q] = (m >> 5) * OS + cpy;
        eox[q] = (m & 31) * OS + cpx;
    }
    #pragma unroll
    for (int nt = 0; nt < NT; nt++) {
        int co = nt * 8 + 2 * tg;
        float b0 = __ldg(bias + co), b1 = __ldg(bias + co + 1);
        #pragma unroll
        for (int mt = 0; mt < 2; mt++) {
            #pragma unroll
            for (int hh = 0; hh < 2; hh++) {
                int qd = mt * 2 + hh;
                float v0 = acc[nt][mt][hh * 2 + 0] + b0;
                float v1 = acc[nt][mt][hh * 2 + 1] + b1;
                if (RELU) { v0 = fmaxf(v0, 0.f); v1 = fmaxf(v1, 0.f); }
                long ob = (((long)n * COUT + co) * W + eoy[qd]) * W + eox[qd];
                long ob1 = ob + (long)W * W;
                if (OUTM == 0) {
                    out[ob] = v0; out[ob1] = v1;
                } else if (OUTM == 1) {
                    out[ob]  = __uint_as_float(f2tf32(v0));
                    out[ob1] = __uint_as_float(f2tf32(v1));
                } else {
                    unsigned h0 = f2tf32(v0), h1 = f2tf32(v1);
                    out[ob]  = __uint_as_float(h0);
                    out[ob1] = __uint_as_float(h1);
                    outl[ob]  = __uint_as_float(f2tf32(v0 - __uint_as_float(h0)));
                    outl[ob1] = __uint_as_float(f2tf32(v1 - __uint_as_float(h1)));
                }
            }
        }
    }
}

// ------------------- conv1 (scalar, CIN=1), parity-split tf32 output -------------------
template<int CIN, int HIN, int K, int S, int P, int COUT, int CT, int ST>
__global__ void k_conv1(const float* __restrict__ in, const float* __restrict__ w,
                        const float* __restrict__ bias, float* __restrict__ out) {
    constexpr int HOUT = (HIN + 2 * P - K) / S + 1;
    constexpr int KK = K * K;
    __shared__ float sw[CT * CIN * KK];
    const int co0 = blockIdx.y * CT;
    const int n   = blockIdx.z;
    const int t   = threadIdx.x;
    for (int i = t; i < CT * CIN * KK; i += 256) {
        int c = i / (CIN * KK), rest = i % (CIN * KK);
        sw[i] = w[(co0 + c) * CIN * KK + rest];
    }
    __syncthreads();

    const int p0  = (blockIdx.x * 256 + t) * ST;
    const int oy  = p0 / HOUT;
    const int ox0 = p0 % HOUT;

    float acc[CT][ST];
    #pragma unroll
    for (int c = 0; c < CT; c++) {
        float bv = bias[co0 + c];
        #pragma unroll
        for (int s = 0; s < ST; s++) acc[c][s] = bv;
    }

    const float* ib = in + (long)n * CIN * HIN * HIN;
    for (int ci = 0; ci < CIN; ci++) {
        const float* ic = ib + ci * HIN * HIN;
        #pragma unroll
        for (int ky = 0; ky < K; ky++) {
            int iy = oy * S - P + ky;
            if ((unsigned)iy < (unsigned)HIN) {
                const float* row = ic + iy * HIN;
                #pragma unroll
                for (int kx = 0; kx < K; kx++) {
                    float xv[ST];
                    #pragma unroll
                    for (int s = 0; s < ST; s++) {
                        int ix = (ox0 + s) * S - P + kx;
                        xv[s] = ((unsigned)ix < (unsigned)HIN) ? row[ix] : 0.f;
                    }
                    #pragma unroll
                    for (int c = 0; c < CT; c++) {
                        float wv = sw[(c * CIN + ci) * KK + ky * K + kx];
                        #pragma unroll
                        for (int s = 0; s < ST; s++)
                            acc[c][s] = fmaf(xv[s], wv, acc[c][s]);
                    }
                }
            }
        }
    }

    const int py = oy & 1, u = oy >> 1;
    #pragma unroll
    for (int c = 0; c < CT; c++) {
        #pragma unroll
        for (int s = 0; s < ST; s++) {
            int ox = ox0 + s;
            int plane = py * 2 + (ox & 1);
            long ob = ((((long)n * COUT + co0 + c) * 4 + plane) * 32 + u) * 32 + (ox >> 1);
            float v = fmaxf(acc[c][s], 0.f);
            out[ob] = __uint_as_float(f2tf32(v));
        }
    }
}

// ------------------- deconv2: [256,32,64,64] -> [256,1,128,128], sigmoid -------------------
__global__ void k_deconv2(const float* __restrict__ in, const float* __restrict__ w,
                          const float* __restrict__ bias, float* __restrict__ out) {
    __shared__ float sw[512];
    const int t = threadIdx.x;
    const int n = blockIdx.z;
    for (int i = t; i < 512; i += 256) sw[i] = w[i];
    __syncthreads();

    const int ti = blockIdx.x * 256 + t;
    const int ty = ti >> 4, tx = ti & 15;
    const float bv = __ldg(bias);

    float acc[4][8];
    #pragma unroll
    for (int r = 0; r < 4; r++)
        #pragma unroll
        for (int c = 0; c < 8; c++) acc[r][c] = 0.f;

    const float* ib = in + (long)n * 32 * 4096;
    for (int ci = 0; ci < 32; ci++) {
        const float* ic = ib + ci * 4096;
        float xv[4][6];
        #pragma unroll
        for (int rr = 0; rr < 4; rr++) {
            int iy = 2 * ty - 1 + rr;
            bool vy = (unsigned)iy < 64u;
            const float* row = ic + iy * 64;
            int c0 = 4 * tx - 1;
            xv[rr][0] = (vy && c0 >= 0) ? row[c0] : 0.f;
            if (vy) {
                float4 m4 = *(const float4*)(row + 4 * tx);
                xv[rr][1] = m4.x; xv[rr][2] = m4.y; xv[rr][3] = m4.z; xv[rr][4] = m4.w;
            } else {
                xv[rr][1] = xv[rr][2] = xv[rr][3] = xv[rr][4] = 0.f;
            }
            int c5 = 4 * tx + 4;
            xv[rr][5] = (vy && c5 < 64) ? row[c5] : 0.f;
        }
        float wr[16];
        #pragma unroll
        for (int k = 0; k < 16; k++) wr[k] = sw[ci * 16 + k];
        #pragma unroll
        for (int r = 0; r < 4; r++) {
            const int pyy = r & 1;
            const int rowA = (r >> 1) + pyy + 1, rowB = rowA - 1;
            #pragma unroll
            for (int c = 0; c < 8; c++) {
                const int pxx = c & 1;
                const int colA = (c >> 1) + pxx + 1, colB = colA - 1;
                float a = acc[r][c];
                a = fmaf(xv[rowA][colA], wr[(1 - pyy) * 4 + (1 - pxx)], a);
                a = fmaf(xv[rowA][colB], wr[(1 - pyy) * 4 + (3 - pxx)], a);
                a = fmaf(xv[rowB][colA], wr[(3 - pyy) * 4 + (1 - pxx)], a);
                a = fmaf(xv[rowB][colB], wr[(3 - pyy) * 4 + (3 - pxx)], a);
                acc[r][c] = a;
            }
        }
    }

    float* ob = out + (long)n * 16384;
    #pragma unroll
    for (int r = 0; r < 4; r++) {
        int oy = 4 * ty + r;
        float v[8];
        #pragma unroll
        for (int c = 0; c < 8; c++)
            v[c] = 1.f / (1.f + expf(-(acc[r][c] + bv)));
        *(float4*)(ob + oy * 128 + 8 * tx)     = make_float4(v[0], v[1], v[2], v[3]);
        *(float4*)(ob + oy * 128 + 8 * tx + 4) = make_float4(v[4], v[5], v[6], v[7]);
    }
}

// ------------------- VQ on tensor cores (1xTF32 distances; exact-z loss) -------------------
__global__ void k_vq_tc(const float* __restrict__ zh, const float* __restrict__ zl,
                        const float* __restrict__ cb, const float* __restrict__ cbh,
                        const float* __restrict__ cn,
                        float* __restrict__ q, float* __restrict__ lpart) {
    __shared__ unsigned As[32][136];
    __shared__ unsigned Bs[32][40];
    __shared__ float scn[32];
    __shared__ int sidx[128];
    __shared__ float red[256];
    const int t = threadIdx.x, lane = t & 31, wrp = t >> 5;
    const int g = lane >> 2, tg = lane & 3;
    const int n  = blockIdx.x >> 3;
    const int p0 = (blockIdx.x & 7) * 128;
    const int mw = wrp * 16;

    for (int i = t; i < 4096; i += 256) {
        int d = i >> 7, m = i & 127;
        long zi = ((long)n * 32 + d) * 1024 + p0 + m;
        As[d][m] = __float_as_uint(zh[zi]);
    }
    __syncthreads();

    unsigned ah[4][4];
    #pragma unroll
    for (int s = 0; s < 4; s++) {
        ah[s][0] = As[s * 8 + tg][mw + g];     ah[s][1] = As[s * 8 + tg][mw + g + 8];
        ah[s][2] = As[s * 8 + tg + 4][mw + g]; ah[s][3] = As[s * 8 + tg + 4][mw + g + 8];
    }

    float best0 = 3.4e38f, best1 = 3.4e38f;
    int bidx0 = 0, bidx1 = 0;

    for (int ch = 0; ch < 16; ch++) {
        const int k0 = ch * 32;
        __syncthreads();
        for (int i = t; i < 1024; i += 256) {
            int d = i & 31, kk = i >> 5;
            Bs[d][kk] = __float_as_uint(cbh[(k0 + kk) * 32 + d]);
        }
        if (t < 32) scn[t] = cn[k0 + t];
        __syncthreads();

        #pragma unroll
        for (int nt = 0; nt < 4; nt++) {
            float a0 = 0.f, a1 = 0.f, a2 = 0.f, a3 = 0.f;
            #pragma unroll
            for (int s = 0; s < 4; s++) {
                unsigned bh0 = Bs[s * 8 + tg][nt * 8 + g];
                unsigned bh1 = Bs[s * 8 + tg + 4][nt * 8 + g];
                mma_tf32(a0, a1, a2, a3, ah[s][0], ah[s][1], ah[s][2], ah[s][3], bh0, bh1);
            }
            int kc0 = k0 + nt * 8 + 2 * tg, kc1 = kc0 + 1;
            float c0 = scn[nt * 8 + 2 * tg], c1 = scn[nt * 8 + 2 * tg + 1];
            float d00 = fmaf(-2.f, a0, c0), d01 = fmaf(-2.f, a1, c1);
            float d10 = fmaf(-2.f, a2, c0), d11 = fmaf(-2.f, a3, c1);
            if (d00 < best0) { best0 = d00; bidx0 = kc0; }
            if (d01 < best0) { best0 = d01; bidx0 = kc1; }
            if (d10 < best1) { best1 = d10; bidx1 = kc0; }
            if (d11 < best1) { best1 = d11; bidx1 = kc1; }
        }
    }

    #pragma unroll
    for (int off = 1; off < 4; off <<= 1) {
        float ob; int oi;
        ob = __shfl_down_sync(0xffffffffu, best0, off, 4);
        oi = __shfl_down_sync(0xffffffffu, bidx0, off, 4);
        if (ob < best0 || (ob == best0 && oi < bidx0)) { best0 = ob; bidx0 = oi; }
        ob = __shfl_down_sync(0xffffffffu, best1, off, 4);
        oi = __shfl_down_sync(0xffffffffu, bidx1, off, 4);
        if (ob < best1 || (ob == best1 && oi < bidx1)) { best1 = ob; bidx1 = oi; }
    }
    if (tg == 0) { sidx[mw + g] = bidx0; sidx[mw + g + 8] = bidx1; }
    __syncthreads();

    float lsum = 0.f;
    for (int i = t; i < 4096; i += 256) {
        int d = i >> 7, m = i & 127;
        long zi = ((long)n * 32 + d) * 1024 + p0 + m;
        float qv = __ldg(cb + sidx[m] * 32 + d);
        float zv = zh[zi] + zl[zi];
        q[zi] = __uint_as_float(f2tf32(qv));
        float e = qv - zv;
        lsum = fmaf(e, e, lsum);
    }
    red[t] = lsum;
    __syncthreads();
    for (int s = 128; s > 0; s >>= 1) {
        if (t < s) red[t] += red[t + s];
        __syncthreads();
    }
    if (t == 0) lpart[blockIdx.x] = red[0];
}

// deterministic fixed-order final reduction: vq_loss = 1.26 * mean
__global__ void k_loss(const float* __restrict__ lpart, float* __restrict__ out,
                       int out_size) {
    __shared__ float red[256];
    const int t = threadIdx.x;
    float s = 0.f;
    #pragma unroll
    for (int j = 0; j < 8; j++) s += lpart[t + 256 * j];
    red[t] = s;
    __syncthreads();
    for (int st = 128; st > 0; st >>= 1) {
        if (t < st) red[t] += red[t + st];
        __syncthreads();
    }
    if (t == 0) out[out_size - 1] = 1.26f * red[0] / 8388608.0f;
}

// ------------------- launch -------------------
extern "C" void kernel_launch(void* const* d_in, const int* in_sizes, int n_in,
                              void* d_out, int out_size) {
    const float* x   = (const float*)d_in[0];
    const float* ew1 = (const float*)d_in[1];  const float* eb1 = (const float*)d_in[2];
    const float* ew2 = (const float*)d_in[3];  const float* eb2 = (const float*)d_in[4];
    const float* ew3 = (const float*)d_in[5];  const float* eb3 = (const float*)d_in[6];
    const float* ew4 = (const float*)d_in[7];  const float* eb4 = (const float*)d_in[8];
    const float* cb  = (const float*)d_in[9];
    const float* dw1 = (const float*)d_in[10]; const float* db1 = (const float*)d_in[11];
    const float* tw1 = (const float*)d_in[12]; const float* tb1 = (const float*)d_in[13];
    const float* tw2 = (const float*)d_in[14]; const float* tb2 = (const float*)d_in[15];
    float* out = (float*)d_out;

    float *pa, *pb, *pc, *pz, *pzl, *pq, *pl, *pwb, *pcbh, *pcn;
    cudaGetSymbolAddress((void**)&pa,  g_a);
    cudaGetSymbolAddress((void**)&pb,  g_b);
    cudaGetSymbolAddress((void**)&pc,  g_c);
    cudaGetSymbolAddress((void**)&pz,  g_z);   cudaGetSymbolAddress((void**)&pzl, g_zl);
    cudaGetSymbolAddress((void**)&pq,  g_q);
    cudaGetSymbolAddress((void**)&pl,  g_lpart);
    cudaGetSymbolAddress((void**)&pwb, g_wb);
    cudaGetSymbolAddress((void**)&pcbh, g_cbh);
    cudaGetSymbolAddress((void**)&pcn, g_cn);

    auto kc2 = k_igemm<32, 32, 64, 1, 2, 0, 4, false, true,  1, 32, true,  1>;
    auto kc3 = k_igemm<64, 32, 64, 1, 3, 1, 9, false, false, 1, 32, true,  1>;
    auto kc4 = k_igemm<64, 32, 32, 1, 1, 0, 1, false, false, 1, 32, false, 2>;
    auto kd1 = k_igemm<32, 32, 64, 1, 3, 1, 9, false, false, 1, 32, true,  1>;
    auto kt1 = k_igemm<64, 32, 32, 1, 1, 0, 4, true,  false, 2, 64, true,  0>;
    const int SM_C2 = 41472, SM_C3 = 64512, SM_C4 = 19456, SM_D1 = 64512, SM_T1 = 33280;
    cudaFuncSetAttribute(kc2, cudaFuncAttributeMaxDynamicSharedMemorySize, SM_C2);
    cudaFuncSetAttribute(kc3, cudaFuncAttributeMaxDynamicSharedMemorySize, SM_C3);
    cudaFuncSetAttribute(kc4, cudaFuncAttributeMaxDynamicSharedMemorySize, SM_C4);
    cudaFuncSetAttribute(kd1, cudaFuncAttributeMaxDynamicSharedMemorySize, SM_D1);
    cudaFuncSetAttribute(kt1, cudaFuncAttributeMaxDynamicSharedMemorySize, SM_T1);

    k_prep_all<<<546, 256>>>(ew2, ew3, ew4, dw1, tw1, cb, pwb, pcbh, pcn);

    // Encoder (conv1 writes parity-split tf32 planes for conv2)
    k_conv1<1, 128, 4, 2, 1, 32, 8, 4><<<dim3(4, 4, BATCH), 256>>>(x, ew1, eb1, pa);
    kc2<<<dim3(4, 1, BATCH), 256, SM_C2>>>(pa, pwb + OFF_C2, eb2, pb, pb);
    kc3<<<dim3(4, 1, BATCH), 256, SM_C3>>>(pb, pwb + OFF_C3, eb3, pc, pc);
    kc4<<<dim3(4, 1, BATCH), 256, SM_C4>>>(pc, pwb + OFF_C4, eb4, pz, pzl);

    // VQ (1xTF32 distances; loss exact in z via hi+lo)
    k_vq_tc<<<2048, 256>>>(pz, pzl, cb, pcbh, pcn, pq, pl);

    // Decoder
    kd1<<<dim3(4, 1, BATCH), 256, SM_D1>>>(pq, pwb + OFF_D1, db1, pc, pc);
    kt1<<<dim3(4, 4, BATCH), 256, SM_T1>>>(pc, pwb + OFF_T1, tb1, pa, pa);
    k_deconv2<<<dim3(2, 1, BATCH), 256>>>(pa, tw2, tb2, out);

    k_loss<<<1, 256>>>(pl, out, out_size);
}

// round 15
// speedup vs baseline: 2.4277x; 1.1528x over previous
#include <cuda_runtime.h>
#include <math.h>

#define BATCH 256

// ------------------- scratch (alloc-free rule: device globals) -------------------
__device__ float g_a [BATCH * 32 * 64 * 64];  // conv1 out (parity-split, tf32) / deconv1 out
__device__ float g_b [BATCH * 64 * 32 * 32];  // conv2 out (tf32)
__device__ float g_c [BATCH * 64 * 32 * 32];  // conv3 out (tf32) / dec1 out (tf32)
__device__ float g_z [BATCH * 32 * 32 * 32];  // z hi
__device__ float g_zl[BATCH * 32 * 32 * 32];  // z lo
__device__ float g_q [BATCH * 32 * 32 * 32];  // quantized latent (tf32-rounded)
__device__ float g_lpart[2048];               // per-block loss partials
__device__ float g_wb [131072];               // prepped weights (tf32), group-major
__device__ float g_cbh[16384];                // codebook (tf32)
__device__ float g_cn[512];                   // codebook norms (fp32)

// group-major layout: [grp][tap][cig(8)][co]   (conv2: [grp][plane][tap][cig][co])
#define OFF_C2  0
#define OFF_C3  32768
#define OFF_C4  69632
#define OFF_D1  71680
#define OFF_T1  90112

// ------------------- helpers -------------------
__device__ __forceinline__ unsigned f2tf32(float x) {
    unsigned r;
    asm("cvt.rna.tf32.f32 %0, %1;" : "=r"(r) : "f"(x));
    return r;
}

__device__ __forceinline__ void mma_tf32(float& c0, float& c1, float& c2, float& c3,
                                         unsigned a0, unsigned a1, unsigned a2, unsigned a3,
                                         unsigned b0, unsigned b1) {
    asm volatile("mma.sync.aligned.m16n8k8.row.col.f32.tf32.tf32.f32 "
                 "{%0,%1,%2,%3}, {%4,%5,%6,%7}, {%8,%9}, {%0,%1,%2,%3};"
                 : "+f"(c0), "+f"(c1), "+f"(c2), "+f"(c3)
                 : "r"(a0), "r"(a1), "r"(a2), "r"(a3), "r"(b0), "r"(b1));
}

__device__ __forceinline__ void cp_async4(unsigned saddr, const float* gptr, int okbytes) {
    asm volatile("cp.async.ca.shared.global [%0], [%1], 4, %2;"
                 :: "r"(saddr), "l"(gptr), "r"(okbytes));
}
__device__ __forceinline__ void cp_commit() {
    asm volatile("cp.async.commit_group;");
}
template<int N>
__device__ __forceinline__ void cp_wait() {
    asm volatile("cp.async.wait_group %0;" :: "n"(N));
}

__host__ __device__ constexpr int calc_pw(int h, int w) {
    int p = w;
    while (((h * p) & 31) != 8) p++;
    return p;
}

// ------------------- fused prep: weights (group-major tf32), codebook, norms -------------------
__global__ void k_prep_all(const float* __restrict__ ew2, const float* __restrict__ ew3,
                           const float* __restrict__ ew4, const float* __restrict__ dw1,
                           const float* __restrict__ tw1, const float* __restrict__ cb,
                           float* __restrict__ wbh, float* __restrict__ cbh,
                           float* __restrict__ cn) {
    const int b = blockIdx.x, t = threadIdx.x;
    float v; int oidx;
    if (b < 128) {                       // conv2 parity-split: [grp4][plane4][tap4][cig8][co64]
        int i = b * 256 + t;
        int co = i & 63, r = i >> 6, cig = r & 7, r2 = r >> 3;
        int tap = r2 & 3, r3 = r2 >> 2, plane = r3 & 3, grp = r3 >> 2;
        int py = plane >> 1, px = plane & 1;
        int ty = tap >> 1, tx = tap & 1;
        int ky = (py == 0) ? (ty ? 3 : 1) : (ty ? 2 : 0);
        int kx = (px == 0) ? (tx ? 3 : 1) : (tx ? 2 : 0);
        int ci = grp * 8 + cig;
        v = ew2[(co * 32 + ci) * 16 + ky * 4 + kx]; oidx = OFF_C2 + i;
    } else if (b < 272) {                // conv3: [grp8][tap9][cig8][co64]
        int i = (b - 128) * 256 + t;
        int co = i & 63, r = i >> 6, cig = r & 7, r2 = r >> 3, tap = r2 % 9, grp = r2 / 9;
        int ci = grp * 8 + cig;
        v = ew3[(co * 64 + ci) * 9 + tap]; oidx = OFF_C3 + i;
    } else if (b < 280) {                // conv4: [grp8][cig8][co32]
        int i = (b - 272) * 256 + t;
        int co = i & 31, r = i >> 5, cig = r & 7, grp = r >> 3;
        int ci = grp * 8 + cig;
        v = ew4[co * 64 + ci]; oidx = OFF_C4 + i;
    } else if (b < 352) {                // dec1: [grp4][tap9][cig8][co64]
        int i = (b - 280) * 256 + t;
        int co = i & 63, r = i >> 6, cig = r & 7, r2 = r >> 3, tap = r2 % 9, grp = r2 / 9;
        int ci = grp * 8 + cig;
        v = dw1[(co * 32 + ci) * 9 + tap]; oidx = OFF_D1 + i;
    } else if (b < 480) {                // deconv1: [cls4][grp8][tap4][cig8][co32]
        int i = (b - 352) * 256 + t;
        int co = i & 31, r = i >> 5, cig = r & 7, r2 = r >> 3, tap = r2 & 3, r3 = r2 >> 2;
        int grp = r3 & 7, cls = r3 >> 3;
        int py = cls >> 1, px = cls & 1;
        int ty = tap >> 1, tx = tap & 1;
        int ky = ty ? 3 - py : 1 - py;
        int kx = tx ? 3 - px : 1 - px;
        int ci = grp * 8 + cig;
        v = tw1[(ci * 32 + co) * 16 + ky * 4 + kx]; oidx = OFF_T1 + i;
    } else if (b < 544) {                // codebook tf32
        int i = (b - 480) * 256 + t;
        cbh[i] = __uint_as_float(f2tf32(cb[i]));
        return;
    } else {                             // norms
        int k = (b - 544) * 256 + t;
        if (k < 512) {
            float s = 0.f;
            const float* c = cb + k * 32;
            #pragma unroll
            for (int d = 0; d < 32; d++) s = fmaf(c[d], c[d], s);
            cn[k] = s;
        }
        return;
    }
    wbh[oidx] = __uint_as_float(f2tf32(v));
}

// ------------------- tf32 implicit-GEMM, cp.async double-buffer, hoisted staging -------------------
// M-tile 256 (8 warps x 2 m16). Pipeline: issue stage(g+1) async, wait stage(g),
// compute taps. Staging loops: element-outer / channel-inner so index math is
// amortized 8x (pure pointer increments in the inner loop).
// PSPLIT: stride-2 conv as 4 stride-1 2x2 convs on parity planes.
// OUTM: 0 fp32, 1 tf32-rounded, 2 hi/lo dual (for VQ).
template<int CIN, int HIN, int COUT, int S, int K, int P, int NTAPS,
         bool DECONV, bool PSPLIT, int OS, int W, bool RELU, int OUTM>
__global__ void __launch_bounds__(256, 2)
k_igemm(const float* __restrict__ in, const float* __restrict__ wbh,
        const float* __restrict__ bias,
        float* __restrict__ out, float* __restrict__ outl) {
    constexpr int G8 = CIN / 8;
    constexpr int NG = PSPLIT ? G8 * 4 : G8;
    constexpr int NT = COUT / 8;
    constexpr int HH = PSPLIT ? 9  : 7 * S + (DECONV ? 2 : K);
    constexpr int HW = PSPLIT ? 33 : 31 * S + (DECONV ? 2 : K);
    constexpr int PW = calc_pw(HH, HW);
    constexpr int CHS = HH * PW;
    constexpr int BP = COUT + 8;
    constexpr int ASZ = 8 * CHS;
    constexpr int BSZ = NTAPS * 8 * BP;
    constexpr int BUF = ASZ + BSZ;
    constexpr int AS = PSPLIT ? 1 : S;
    constexpr int GCH = PSPLIT ? 4 * HIN * HIN : HIN * HIN;  // gmem channel stride

    extern __shared__ float sm[];

    const int t = threadIdx.x, lane = t & 31, wrp = t >> 5;
    const int g = lane >> 2, tg = lane & 3;
    const int n = blockIdx.z;
    const int m0 = blockIdx.x * 256;
    const int r0 = blockIdx.x * 8;

    int cpy = 0, cpx = 0, cls = 0;
    if (DECONV) { cls = blockIdx.y; cpy = cls >> 1; cpx = cls & 1; }

    int aoff[4];
    #pragma unroll
    for (int q = 0; q < 4; q++) {
        int ml = wrp * 32 + (q >> 1) * 16 + g + (q & 1) * 8;
        int oyl = ml >> 5, ox = ml & 31;
        aoff[q] = tg * CHS + (oyl * AS) * PW + ox * AS;
    }
    const int btg = tg * BP, btg4 = (tg + 4) * BP;

    float acc[NT][2][4];
    #pragma unroll
    for (int i = 0; i < NT; i++)
        #pragma unroll
        for (int mt = 0; mt < 2; mt++)
            #pragma unroll
            for (int j = 0; j < 4; j++) acc[i][mt][j] = 0.f;

    // async stage of one subgroup into buffer buf (element-outer, channel-inner)
    auto stage = [&](int sg, int buf) {
        const int grp   = PSPLIT ? (sg >> 2) : sg;
        const int plane = PSPLIT ? (sg & 3) : 0;
        const int DYMIN = PSPLIT ? -(plane >> 1) : (DECONV ? cpy - 1 : -P);
        const int DXMIN = PSPLIT ? -(plane & 1)  : (DECONV ? cpx - 1 : -P);
        const int ci0 = grp * 8;
        unsigned abase = (unsigned)__cvta_generic_to_shared(sm + buf * BUF);
        const long gch0 = PSPLIT
            ? (((long)n * CIN + ci0) * 4 + plane) * (HIN * HIN)
            : ((long)n * CIN + ci0) * (HIN * HIN);
        const int ybase = (PSPLIT ? r0 : r0 * S) + DYMIN;
        // A halo: element-outer, channel-inner
        for (int e = t; e < HH * HW; e += 256) {
            int rr = e / HW, cc = e % HW;
            int iy = ybase + rr;
            int ix = DXMIN + cc;
            int okb = ((unsigned)iy < (unsigned)HIN && (unsigned)ix < (unsigned)HIN) ? 4 : 0;
            const float* gp = in + gch0 + (long)iy * HIN + ix;
            unsigned sa = abase + (unsigned)(rr * PW + cc) * 4u;
            #pragma unroll
            for (int ch = 0; ch < 8; ch++)
                cp_async4(sa + ch * (CHS * 4), gp + (long)ch * GCH, okb);
        }
        // B: element-outer, tap-inner
        unsigned bbase = abase + ASZ * 4;
        const long wo = (DECONV ? (long)cls * NG * NTAPS * 8 * COUT : 0)
                      + (long)sg * NTAPS * 8 * COUT;
        for (int e = t; e < 8 * COUT; e += 256) {
            int k = e / COUT, co = e % COUT;
            unsigned sb = bbase + (unsigned)(k * BP + co) * 4u;
            const float* gp = wbh + wo + e;
            #pragma unroll
            for (int tap = 0; tap < NTAPS; tap++)
                cp_async4(sb + tap * (8 * BP * 4), gp + tap * (8 * COUT), 4);
        }
        cp_commit();
    };

    stage(0, 0);
    for (int sg = 0; sg < NG; sg++) {
        const int b = sg & 1;
        if (sg + 1 < NG) { stage(sg + 1, b ^ 1); cp_wait<1>(); }
        else             { cp_wait<0>(); }
        __syncthreads();

        const float* Ab = sm + b * BUF;
        const float* Bb = Ab + ASZ;

        for (int tap = 0; tap < NTAPS; tap++) {
            int ty, tx;
            if (PSPLIT)      { ty = tap >> 1;            tx = tap & 1; }
            else if (DECONV) { ty = 1 - (tap >> 1);      tx = 1 - (tap & 1); }
            else             { ty = tap / K;             tx = tap % K; }
            const int toff = ty * PW + tx;

            unsigned ah[2][4];
            #pragma unroll
            for (int q = 0; q < 4; q++) {
                int si = aoff[q] + toff;
                int mt = q >> 1, h = q & 1;
                ah[mt][h]     = __float_as_uint(Ab[si]);
                ah[mt][2 + h] = __float_as_uint(Ab[si + 4 * CHS]);
            }

            const float* Bth = Bb + tap * 8 * BP;
            unsigned pbh0 = __float_as_uint(Bth[btg + g]);
            unsigned pbh1 = __float_as_uint(Bth[btg4 + g]);
            #pragma unroll
            for (int nt = 0; nt < NT; nt++) {
                unsigned bh0 = pbh0, bh1 = pbh1;
                if (nt + 1 < NT) {
                    pbh0 = __float_as_uint(Bth[btg + (nt + 1) * 8 + g]);
                    pbh1 = __float_as_uint(Bth[btg4 + (nt + 1) * 8 + g]);
                }
                #pragma unroll
                for (int mt = 0; mt < 2; mt++)
                    mma_tf32(acc[nt][mt][0], acc[nt][mt][1], acc[nt][mt][2], acc[nt][mt][3],
                             ah[mt][0], ah[mt][1], ah[mt][2], ah[mt][3], bh0, bh1);
            }
        }
        __syncthreads();
    }

    // ---- epilogue: direct strided stores ----
    int eoy[4], eox[4];
    #pragma unroll
    for (int q = 0; q < 4; q++) {
        int m = m0 + wrp * 32 + (q >> 1) * 16 + ((q & 1) ? g + 8 : g);
        eoy[q] = (m >> 5) * OS + cpy;
        eox[q] = (m & 31) * OS + cpx;
    }
    #pragma unroll
    for (int nt = 0; nt < NT; nt++) {
        int co = nt * 8 + 2 * tg;
        float b0 = __ldg(bias + co), b1 = __ldg(bias + co + 1);
        #pragma unroll
        for (int mt = 0; mt < 2; mt++) {
            #pragma unroll
            for (int hh = 0; hh < 2; hh++) {
                int qd = mt * 2 + hh;
                float v0 = acc[nt][mt][hh * 2 + 0] + b0;
                float v1 = acc[nt][mt][hh * 2 + 1] + b1;
                if (RELU) { v0 = fmaxf(v0, 0.f); v1 = fmaxf(v1, 0.f); }
                long ob = (((long)n * COUT + co) * W + eoy[qd]) * W + eox[qd];
                long ob1 = ob + (long)W * W;
                if (OUTM == 0) {
                    out[ob] = v0; out[ob1] = v1;
                } else if (OUTM == 1) {
                    out[ob]  = __uint_as_float(f2tf32(v0));
                    out[ob1] = __uint_as_float(f2tf32(v1));
                } else {
                    unsigned h0 = f2tf32(v0), h1 = f2tf32(v1);
                    out[ob]  = __uint_as_float(h0);
                    out[ob1] = __uint_as_float(h1);
                    outl[ob]  = __uint_as_float(f2tf32(v0 - __uint_as_float(h0)));
                    outl[ob1] = __uint_as_float(f2tf32(v1 - __uint_as_float(h1)));
                }
            }
        }
    }
}

// ------------------- conv1 (scalar, CIN=1), parity-split tf32 output -------------------
template<int CIN, int HIN, int K, int S, int P, int COUT, int CT, int ST>
__global__ void k_conv1(const float* __restrict__ in, const float* __restrict__ w,
                        const float* __restrict__ bias, float* __restrict__ out) {
    constexpr int HOUT = (HIN + 2 * P - K) / S + 1;
    constexpr int KK = K * K;
    __shared__ float sw[CT * CIN * KK];
    const int co0 = blockIdx.y * CT;
    const int n   = blockIdx.z;
    const int t   = threadIdx.x;
    for (int i = t; i < CT * CIN * KK; i += 256) {
        int c = i / (CIN * KK), rest = i % (CIN * KK);
        sw[i] = w[(co0 + c) * CIN * KK + rest];
    }
    __syncthreads();

    const int p0  = (blockIdx.x * 256 + t) * ST;
    const int oy  = p0 / HOUT;
    const int ox0 = p0 % HOUT;

    float acc[CT][ST];
    #pragma unroll
    for (int c = 0; c < CT; c++) {
        float bv = bias[co0 + c];
        #pragma unroll
        for (int s = 0; s < ST; s++) acc[c][s] = bv;
    }

    const float* ib = in + (long)n * CIN * HIN * HIN;
    for (int ci = 0; ci < CIN; ci++) {
        const float* ic = ib + ci * HIN * HIN;
        #pragma unroll
        for (int ky = 0; ky < K; ky++) {
            int iy = oy * S - P + ky;
            if ((unsigned)iy < (unsigned)HIN) {
                const float* row = ic + iy * HIN;
                #pragma unroll
                for (int kx = 0; kx < K; kx++) {
                    float xv[ST];
                    #pragma unroll
                    for (int s = 0; s < ST; s++) {
                        int ix = (ox0 + s) * S - P + kx;
                        xv[s] = ((unsigned)ix < (unsigned)HIN) ? row[ix] : 0.f;
                    }
                    #pragma unroll
                    for (int c = 0; c < CT; c++) {
                        float wv = sw[(c * CIN + ci) * KK + ky * K + kx];
                        #pragma unroll
                        for (int s = 0; s < ST; s++)
                            acc[c][s] = fmaf(xv[s], wv, acc[c][s]);
                    }
                }
            }
        }
    }

    const int py = oy & 1, u = oy >> 1;
    #pragma unroll
    for (int c = 0; c < CT; c++) {
        #pragma unroll
        for (int s = 0; s < ST; s++) {
            int ox = ox0 + s;
            int plane = py * 2 + (ox & 1);
            long ob = ((((long)n * COUT + co0 + c) * 4 + plane) * 32 + u) * 32 + (ox >> 1);
            float v = fmaxf(acc[c][s], 0.f);
            out[ob] = __uint_as_float(f2tf32(v));
        }
    }
}

// ------------------- deconv2: [256,32,64,64] -> [256,1,128,128], sigmoid -------------------
__global__ void k_deconv2(const float* __restrict__ in, const float* __restrict__ w,
                          const float* __restrict__ bias, float* __restrict__ out) {
    __shared__ float sw[512];
    const int t = threadIdx.x;
    const int n = blockIdx.z;
    for (int i = t; i < 512; i += 256) sw[i] = w[i];
    __syncthreads();

    const int ti = blockIdx.x * 256 + t;
    const int ty = ti >> 4, tx = ti & 15;
    const float bv = __ldg(bias);

    float acc[4][8];
    #pragma unroll
    for (int r = 0; r < 4; r++)
        #pragma unroll
        for (int c = 0; c < 8; c++) acc[r][c] = 0.f;

    const float* ib = in + (long)n * 32 * 4096;
    for (int ci = 0; ci < 32; ci++) {
        const float* ic = ib + ci * 4096;
        float xv[4][6];
        #pragma unroll
        for (int rr = 0; rr < 4; rr++) {
            int iy = 2 * ty - 1 + rr;
            bool vy = (unsigned)iy < 64u;
            const float* row = ic + iy * 64;
            int c0 = 4 * tx - 1;
            xv[rr][0] = (vy && c0 >= 0) ? row[c0] : 0.f;
            if (vy) {
                float4 m4 = *(const float4*)(row + 4 * tx);
                xv[rr][1] = m4.x; xv[rr][2] = m4.y; xv[rr][3] = m4.z; xv[rr][4] = m4.w;
            } else {
                xv[rr][1] = xv[rr][2] = xv[rr][3] = xv[rr][4] = 0.f;
            }
            int c5 = 4 * tx + 4;
            xv[rr][5] = (vy && c5 < 64) ? row[c5] : 0.f;
        }
        float wr[16];
        #pragma unroll
        for (int k = 0; k < 16; k++) wr[k] = sw[ci * 16 + k];
        #pragma unroll
        for (int r = 0; r < 4; r++) {
            const int pyy = r & 1;
            const int rowA = (r >> 1) + pyy + 1, rowB = rowA - 1;
            #pragma unroll
            for (int c = 0; c < 8; c++) {
                const int pxx = c & 1;
                const int colA = (c >> 1) + pxx + 1, colB = colA - 1;
                float a = acc[r][c];
                a = fmaf(xv[rowA][colA], wr[(1 - pyy) * 4 + (1 - pxx)], a);
                a = fmaf(xv[rowA][colB], wr[(1 - pyy) * 4 + (3 - pxx)], a);
                a = fmaf(xv[rowB][colA], wr[(3 - pyy) * 4 + (1 - pxx)], a);
                a = fmaf(xv[rowB][colB], wr[(3 - pyy) * 4 + (3 - pxx)], a);
                acc[r][c] = a;
            }
        }
    }

    float* ob = out + (long)n * 16384;
    #pragma unroll
    for (int r = 0; r < 4; r++) {
        int oy = 4 * ty + r;
        float v[8];
        #pragma unroll
        for (int c = 0; c < 8; c++)
            v[c] = 1.f / (1.f + expf(-(acc[r][c] + bv)));
        *(float4*)(ob + oy * 128 + 8 * tx)     = make_float4(v[0], v[1], v[2], v[3]);
        *(float4*)(ob + oy * 128 + 8 * tx + 4) = make_float4(v[4], v[5], v[6], v[7]);
    }
}

// ------------------- VQ on tensor cores (1xTF32 distances; exact-z loss) -------------------
__global__ void k_vq_tc(const float* __restrict__ zh, const float* __restrict__ zl,
                        const float* __restrict__ cb, const float* __restrict__ cbh,
                        const float* __restrict__ cn,
                        float* __restrict__ q, float* __restrict__ lpart) {
    __shared__ unsigned As[32][136];
    __shared__ unsigned Bs[32][40];
    __shared__ float scn[32];
    __shared__ int sidx[128];
    __shared__ float red[256];
    const int t = threadIdx.x, lane = t & 31, wrp = t >> 5;
    const int g = lane >> 2, tg = lane & 3;
    const int n  = blockIdx.x >> 3;
    const int p0 = (blockIdx.x & 7) * 128;
    const int mw = wrp * 16;

    for (int i = t; i < 4096; i += 256) {
        int d = i >> 7, m = i & 127;
        long zi = ((long)n * 32 + d) * 1024 + p0 + m;
        As[d][m] = __float_as_uint(zh[zi]);
    }
    __syncthreads();

    unsigned ah[4][4];
    #pragma unroll
    for (int s = 0; s < 4; s++) {
        ah[s][0] = As[s * 8 + tg][mw + g];     ah[s][1] = As[s * 8 + tg][mw + g + 8];
        ah[s][2] = As[s * 8 + tg + 4][mw + g]; ah[s][3] = As[s * 8 + tg + 4][mw + g + 8];
    }

    float best0 = 3.4e38f, best1 = 3.4e38f;
    int bidx0 = 0, bidx1 = 0;

    for (int ch = 0; ch < 16; ch++) {
        const int k0 = ch * 32;
        __syncthreads();
        for (int i = t; i < 1024; i += 256) {
            int d = i & 31, kk = i >> 5;
            Bs[d][kk] = __float_as_uint(cbh[(k0 + kk) * 32 + d]);
        }
        if (t < 32) scn[t] = cn[k0 + t];
        __syncthreads();

        #pragma unroll
        for (int nt = 0; nt < 4; nt++) {
            float a0 = 0.f, a1 = 0.f, a2 = 0.f, a3 = 0.f;
            #pragma unroll
            for (int s = 0; s < 4; s++) {
                unsigned bh0 = Bs[s * 8 + tg][nt * 8 + g];
                unsigned bh1 = Bs[s * 8 + tg + 4][nt * 8 + g];
                mma_tf32(a0, a1, a2, a3, ah[s][0], ah[s][1], ah[s][2], ah[s][3], bh0, bh1);
            }
            int kc0 = k0 + nt * 8 + 2 * tg, kc1 = kc0 + 1;
            float c0 = scn[nt * 8 + 2 * tg], c1 = scn[nt * 8 + 2 * tg + 1];
            float d00 = fmaf(-2.f, a0, c0), d01 = fmaf(-2.f, a1, c1);
            float d10 = fmaf(-2.f, a2, c0), d11 = fmaf(-2.f, a3, c1);
            if (d00 < best0) { best0 = d00; bidx0 = kc0; }
            if (d01 < best0) { best0 = d01; bidx0 = kc1; }
            if (d10 < best1) { best1 = d10; bidx1 = kc0; }
            if (d11 < best1) { best1 = d11; bidx1 = kc1; }
        }
    }

    #pragma unroll
    for (int off = 1; off < 4; off <<= 1) {
        float ob; int oi;
        ob = __shfl_down_sync(0xffffffffu, best0, off, 4);
        oi = __shfl_down_sync(0xffffffffu, bidx0, off, 4);
        if (ob < best0 || (ob == best0 && oi < bidx0)) { best0 = ob; bidx0 = oi; }
        ob = __shfl_down_sync(0xffffffffu, best1, off, 4);
        oi = __shfl_down_sync(0xffffffffu, bidx1, off, 4);
        if (ob < best1 || (ob == best1 && oi < bidx1)) { best1 = ob; bidx1 = oi; }
    }
    if (tg == 0) { sidx[mw + g] = bidx0; sidx[mw + g + 8] = bidx1; }
    __syncthreads();

    float lsum = 0.f;
    for (int i = t; i < 4096; i += 256) {
        int d = i >> 7, m = i & 127;
        long zi = ((long)n * 32 + d) * 1024 + p0 + m;
        float qv = __ldg(cb + sidx[m] * 32 + d);
        float zv = zh[zi] + zl[zi];
        q[zi] = __uint_as_float(f2tf32(qv));
        float e = qv - zv;
        lsum = fmaf(e, e, lsum);
    }
    red[t] = lsum;
    __syncthreads();
    for (int s = 128; s > 0; s >>= 1) {
        if (t < s) red[t] += red[t + s];
        __syncthreads();
    }
    if (t == 0) lpart[blockIdx.x] = red[0];
}

// deterministic fixed-order final reduction: vq_loss = 1.26 * mean
__global__ void k_loss(const float* __restrict__ lpart, float* __restrict__ out,
                       int out_size) {
    __shared__ float red[256];
    const int t = threadIdx.x;
    float s = 0.f;
    #pragma unroll
    for (int j = 0; j < 8; j++) s += lpart[t + 256 * j];
    red[t] = s;
    __syncthreads();
    for (int st = 128; st > 0; st >>= 1) {
        if (t < st) red[t] += red[t + st];
        __syncthreads();
    }
    if (t == 0) out[out_size - 1] = 1.26f * red[0] / 8388608.0f;
}

// ------------------- launch -------------------
extern "C" void kernel_launch(void* const* d_in, const int* in_sizes, int n_in,
                              void* d_out, int out_size) {
    const float* x   = (const float*)d_in[0];
    const float* ew1 = (const float*)d_in[1];  const float* eb1 = (const float*)d_in[2];
    const float* ew2 = (const float*)d_in[3];  const float* eb2 = (const float*)d_in[4];
    const float* ew3 = (const float*)d_in[5];  const float* eb3 = (const float*)d_in[6];
    const float* ew4 = (const float*)d_in[7];  const float* eb4 = (const float*)d_in[8];
    const float* cb  = (const float*)d_in[9];
    const float* dw1 = (const float*)d_in[10]; const float* db1 = (const float*)d_in[11];
    const float* tw1 = (const float*)d_in[12]; const float* tb1 = (const float*)d_in[13];
    const float* tw2 = (const float*)d_in[14]; const float* tb2 = (const float*)d_in[15];
    float* out = (float*)d_out;

    float *pa, *pb, *pc, *pz, *pzl, *pq, *pl, *pwb, *pcbh, *pcn;
    cudaGetSymbolAddress((void**)&pa,  g_a);
    cudaGetSymbolAddress((void**)&pb,  g_b);
    cudaGetSymbolAddress((void**)&pc,  g_c);
    cudaGetSymbolAddress((void**)&pz,  g_z);   cudaGetSymbolAddress((void**)&pzl, g_zl);
    cudaGetSymbolAddress((void**)&pq,  g_q);
    cudaGetSymbolAddress((void**)&pl,  g_lpart);
    cudaGetSymbolAddress((void**)&pwb, g_wb);
    cudaGetSymbolAddress((void**)&pcbh, g_cbh);
    cudaGetSymbolAddress((void**)&pcn, g_cn);

    auto kc2 = k_igemm<32, 32, 64, 1, 2, 0, 4, false, true,  1, 32, true,  1>;
    auto kc3 = k_igemm<64, 32, 64, 1, 3, 1, 9, false, false, 1, 32, true,  1>;
    auto kc4 = k_igemm<64, 32, 32, 1, 1, 0, 1, false, false, 1, 32, false, 2>;
    auto kd1 = k_igemm<32, 32, 64, 1, 3, 1, 9, false, false, 1, 32, true,  1>;
    auto kt1 = k_igemm<64, 32, 32, 1, 1, 0, 4, true,  false, 2, 64, true,  0>;
    const int SM_C2 = 41472, SM_C3 = 64512, SM_C4 = 19456, SM_D1 = 64512, SM_T1 = 33280;
    cudaFuncSetAttribute(kc2, cudaFuncAttributeMaxDynamicSharedMemorySize, SM_C2);
    cudaFuncSetAttribute(kc3, cudaFuncAttributeMaxDynamicSharedMemorySize, SM_C3);
    cudaFuncSetAttribute(kc4, cudaFuncAttributeMaxDynamicSharedMemorySize, SM_C4);
    cudaFuncSetAttribute(kd1, cudaFuncAttributeMaxDynamicSharedMemorySize, SM_D1);
    cudaFuncSetAttribute(kt1, cudaFuncAttributeMaxDynamicSharedMemorySize, SM_T1);

    k_prep_all<<<546, 256>>>(ew2, ew3, ew4, dw1, tw1, cb, pwb, pcbh, pcn);

    // Encoder (conv1 writes parity-split tf32 planes for conv2)
    k_conv1<1, 128, 4, 2, 1, 32, 8, 4><<<dim3(4, 4, BATCH), 256>>>(x, ew1, eb1, pa);
    kc2<<<dim3(4, 1, BATCH), 256, SM_C2>>>(pa, pwb + OFF_C2, eb2, pb, pb);
    kc3<<<dim3(4, 1, BATCH), 256, SM_C3>>>(pb, pwb + OFF_C3, eb3, pc, pc);
    kc4<<<dim3(4, 1, BATCH), 256, SM_C4>>>(pc, pwb + OFF_C4, eb4, pz, pzl);

    // VQ (1xTF32 distances; loss exact in z via hi+lo)
    k_vq_tc<<<2048, 256>>>(pz, pzl, cb, pcbh, pcn, pq, pl);

    // Decoder
    kd1<<<dim3(4, 1, BATCH), 256, SM_D1>>>(pq, pwb + OFF_D1, db1, pc, pc);
    kt1<<<dim3(4, 4, BATCH), 256, SM_T1>>>(pc, pwb + OFF_T1, tb1, pa, pa);
    k_deconv2<<<dim3(2, 1, BATCH), 256>>>(pa, tw2, tb2, out);

    k_loss<<<1, 256>>>(pl, out, out_size);
}